// round 10
// baseline (speedup 1.0000x reference)
#include <cuda_runtime.h>
#include <cuda_bf16.h>
#include <math.h>
#include <stdint.h>

// ---------------- problem constants ----------------
#define NN 10000
#define EE 160000
#define DN 256
#define DE 512
#define NH 8
#define NC 10
#define KN 5000
#define KE 80000
#define MAXL 80000   // worst-case live edges

// ---------------- device scratch ----------------
__device__ float g_q[(size_t)NN * DE];
__device__ float g_kc[(size_t)MAXL * DE];
__device__ float g_vc[(size_t)MAXL * DE];
__device__ float g_efw1[(size_t)MAXL * DE];
__device__ float g_scc[(size_t)MAXL * NH];
__device__ float g_qbk[(size_t)NN * NH];
__device__ float g_agg[(size_t)NN * DE];
__device__ float g_nt[(size_t)NN * DE];
__device__ float g_outc[(size_t)NN * NC];
__device__ float g_nscore[NN];
__device__ float g_escore[EE];
__device__ unsigned char g_emask8[EE];
__device__ float g_thr[2];
__device__ float g_zb[DE];
// bf16 hi/lo splits
__device__ __nv_bfloat16 g_cefhi[(size_t)MAXL * DE];
__device__ __nv_bfloat16 g_ceflo[(size_t)MAXL * DE];
__device__ __nv_bfloat16 g_nfhi[(size_t)NN * DN];
__device__ __nv_bfloat16 g_nflo[(size_t)NN * DN];
__device__ __nv_bfloat16 g_agghi[(size_t)NN * DE];
__device__ __nv_bfloat16 g_agglo[(size_t)NN * DE];
__device__ __nv_bfloat16 g_awhi[(size_t)NN * DE];
__device__ __nv_bfloat16 g_awlo[(size_t)NN * DE];
// weights: slot 0=Wq(K=256), 1=Wk, 2=Wv, 3=W1, 4=Wo  ([Nout=512, K] K-major)
// slots 1..3 contiguous -> fused N=1536 GEMM over Wk|Wv|W1
__device__ __nv_bfloat16 g_whi[5][DE * DE];
__device__ __nv_bfloat16 g_wlo[5][DE * DE];
// compaction / CSR
__device__ int g_live[MAXL];
__device__ int g_blkcnt[625];
__device__ int g_blkoff[625];
__device__ int g_nlive;
__device__ int g_degt[NN];
__device__ int g_degl[NN];
__device__ int g_off[NN + 1];
__device__ int g_cur[NN];
__device__ int g_elist[MAXL];

// ================= PTX helpers =================
__device__ __forceinline__ void ldm4(uint32_t* r, uint32_t a) {
    asm volatile("ldmatrix.sync.aligned.m8n8.x4.shared.b16 {%0,%1,%2,%3}, [%4];"
                 : "=r"(r[0]), "=r"(r[1]), "=r"(r[2]), "=r"(r[3]) : "r"(a));
}
__device__ __forceinline__ void mma_bf16(float* d, const uint32_t* a, uint32_t b0, uint32_t b1) {
    asm volatile("mma.sync.aligned.m16n8k16.row.col.f32.bf16.bf16.f32 "
                 "{%0,%1,%2,%3},{%4,%5,%6,%7},{%8,%9},{%0,%1,%2,%3};"
                 : "+f"(d[0]), "+f"(d[1]), "+f"(d[2]), "+f"(d[3])
                 : "r"(a[0]), "r"(a[1]), "r"(a[2]), "r"(a[3]), "r"(b0), "r"(b1));
}
__device__ __forceinline__ void cpasync16(uint32_t s, const void* g) {
    asm volatile("cp.async.cg.shared.global [%0], [%1], 16;" :: "r"(s), "l"(g));
}
__device__ __forceinline__ void cp_commit() { asm volatile("cp.async.commit_group;" ::: "memory"); }
#define CP_WAIT(n) asm volatile("cp.async.wait_group %0;" :: "n"(n) : "memory")

__device__ __forceinline__ uint32_t pack2bf(float x, float y) {
    __nv_bfloat162 h = __floats2bfloat162_rn(x, y);
    return *reinterpret_cast<uint32_t*>(&h);
}
__device__ __forceinline__ float gelu_exact(float x) {
    return 0.5f * x * (1.0f + erff(x * 0.70710678118654752f));
}

// ================= prep: all weight transposes+splits, nf split, zeroing =================
__global__ void prep_kernel(const float* __restrict__ Wq, const float* __restrict__ Wk,
                            const float* __restrict__ Wv, const float* __restrict__ W1,
                            const float* __restrict__ Wo, const float* __restrict__ nf)
{
    int idx = blockIdx.x * 256 + threadIdx.x;
    const int S0 = DE * DN;              // 131072
    const int SB = DE * DE;              // 262144
    const int WTOT = S0 + 4 * SB;        // 1179648
    const int NF4 = NN * DN / 4;         // 640000
    if (idx < WTOT) {
        int slot, K, r;
        const float* W;
        if (idx < S0) { slot = 0; K = DN; r = idx; W = Wq; }
        else {
            int t = idx - S0;
            slot = 1 + t / SB;
            r = t % SB; K = DE;
            W = (slot == 1) ? Wk : (slot == 2) ? Wv : (slot == 3) ? W1 : Wo;
        }
        int n = r % DE, k = r / DE;
        float x = W[(size_t)k * DE + n];
        __nv_bfloat16 h = __float2bfloat16(x);
        g_whi[slot][n * K + k] = h;
        g_wlo[slot][n * K + k] = __float2bfloat16(x - __bfloat162float(h));
    } else if (idx < WTOT + NF4) {
        size_t i = idx - WTOT;
        float4 x = reinterpret_cast<const float4*>(nf)[i];
        __nv_bfloat162 h0 = __floats2bfloat162_rn(x.x, x.y);
        __nv_bfloat162 h1 = __floats2bfloat162_rn(x.z, x.w);
        uint2 hv, lv;
        hv.x = *reinterpret_cast<uint32_t*>(&h0);
        hv.y = *reinterpret_cast<uint32_t*>(&h1);
        lv.x = pack2bf(x.x - __bfloat162float(h0.x), x.y - __bfloat162float(h0.y));
        lv.y = pack2bf(x.z - __bfloat162float(h1.x), x.w - __bfloat162float(h1.y));
        reinterpret_cast<uint2*>(g_nfhi)[i] = hv;
        reinterpret_cast<uint2*>(g_nflo)[i] = lv;
    } else {
        int i = idx - WTOT - NF4;
        if (i < NN) { g_degt[i] = 0; g_degl[i] = 0; }
        if (i < DE) g_zb[i] = 0.f;
    }
}

// ================= both scorers in one launch: one warp per row =================
__global__ void score_all_kernel(const float* __restrict__ nf, const float* __restrict__ ef,
                                 const float* __restrict__ nw, const float* __restrict__ nb,
                                 const float* __restrict__ ew, const float* __restrict__ eb)
{
    int warp = (blockIdx.x * blockDim.x + threadIdx.x) >> 5;
    int lane = threadIdx.x & 31;
    if (warp < NN) {
        const float* row = nf + (size_t)warp * DN;
        float s = 0.f;
        for (int k = lane; k < DN; k += 32) s += row[k] * nw[k];
        #pragma unroll
        for (int o = 16; o; o >>= 1) s += __shfl_xor_sync(0xFFFFFFFFu, s, o);
        if (lane == 0) g_nscore[warp] = s + nb[0];
    } else if (warp < NN + EE) {
        int e = warp - NN;
        const float* row = ef + (size_t)e * DE;
        float s = 0.f;
        for (int k = lane; k < DE; k += 32) s += row[k] * ew[k];
        #pragma unroll
        for (int o = 16; o; o >>= 1) s += __shfl_xor_sync(0xFFFFFFFFu, s, o);
        if (lane == 0) g_escore[e] = s + eb[0];
    }
}

// ================= dual top-k (exact 4x8-bit radix; warp-aggregated atomics) =================
__device__ __forceinline__ unsigned f2u_ord(float x) {
    unsigned u = __float_as_uint(x);
    return (u & 0x80000000u) ? ~u : (u | 0x80000000u);
}
__global__ void topk_kernel() {
    int b = blockIdx.x;                       // 0: nodes, 1: edges
    const float* data = b ? g_escore : g_nscore;
    int n = b ? EE : NN;
    unsigned k = b ? KE : KN;
    __shared__ unsigned hist[256];
    __shared__ unsigned prefix_s, krem_s;
    int tid = threadIdx.x;
    int lane = tid & 31;
    if (tid == 0) { prefix_s = 0u; krem_s = k; }
    __syncthreads();
    int nIter = (n + blockDim.x - 1) / blockDim.x;
    for (int shift = 24; shift >= 0; shift -= 8) {
        if (tid < 256) hist[tid] = 0u;
        __syncthreads();
        unsigned prefix = prefix_s;
        unsigned maskhi = (shift == 24) ? 0u : (0xFFFFFFFFu << (shift + 8));
        for (int it = 0; it < nIter; it++) {
            int i = it * blockDim.x + tid;
            bool ok = false; unsigned dig = 0;
            if (i < n) {
                unsigned u = f2u_ord(data[i]);
                ok = ((u & maskhi) == prefix);
                dig = (u >> shift) & 255u;
            }
            unsigned key = ok ? dig : 0xFFFFFFFFu;
            unsigned grp = __match_any_sync(0xFFFFFFFFu, key);
            if (ok && lane == (__ffs(grp) - 1))
                atomicAdd(&hist[dig], (unsigned)__popc(grp));
        }
        __syncthreads();
        if (tid == 0) {
            unsigned krem = krem_s, cum = 0; int digit = 0;
            for (int d = 255; d >= 0; d--) {
                unsigned c = hist[d];
                if (cum + c >= krem) { digit = d; break; }
                cum += c;
            }
            prefix_s |= ((unsigned)digit) << shift;
            krem_s = krem - cum;
        }
        __syncthreads();
    }
    if (tid == 0) {
        unsigned u = prefix_s;
        u = (u & 0x80000000u) ? (u & 0x7FFFFFFFu) : ~u;
        g_thr[b] = __uint_as_float(u);
    }
}

// ================= edge mask + degree counts + per-block live counts =================
__global__ void emask_count_kernel(const int* __restrict__ src, const int* __restrict__ dst) {
    int e = blockIdx.x * 256 + threadIdx.x;
    bool live = false;
    if (e < EE) {
        float tn = g_thr[0], te = g_thr[1];
        live = (g_escore[e] >= te) && (g_nscore[src[e]] >= tn) && (g_nscore[dst[e]] >= tn);
        g_emask8[e] = live ? 1 : 0;
        atomicAdd(&g_degt[src[e]], 1);
        if (live) atomicAdd(&g_degl[src[e]], 1);
    }
    int cnt = __syncthreads_count(live);
    if (threadIdx.x == 0) g_blkcnt[blockIdx.x] = cnt;
}

// ================= scans =================
__global__ void scan2_kernel() {   // 1 block, 1024 threads
    int t = threadIdx.x;
    if (t == 0) {
        int run = 0;
        for (int i = 0; i < 625; i++) { g_blkoff[i] = run; run += g_blkcnt[i]; }
        g_nlive = run > MAXL ? MAXL : run;
    }
    __syncthreads();
    __shared__ int part[1024];
    const int CH = (NN + 1023) / 1024;
    int s = 0;
    for (int j = 0; j < CH; j++) { int i = t * CH + j; if (i < NN) s += g_degl[i]; }
    part[t] = s;
    __syncthreads();
    if (t == 0) {
        int run = 0;
        for (int i = 0; i < 1024; i++) { int v = part[i]; part[i] = run; run += v; }
        g_off[NN] = run;
    }
    __syncthreads();
    int run = part[t];
    for (int j = 0; j < CH; j++) {
        int i = t * CH + j;
        if (i < NN) { g_off[i] = run; g_cur[i] = run; run += g_degl[i]; }
    }
}

// ================= deterministic order-preserving compaction =================
__global__ void compact_kernel() {
    int e = blockIdx.x * 256 + threadIdx.x;
    bool m = (e < EE) && g_emask8[e];
    int wid = threadIdx.x >> 5, lane = threadIdx.x & 31;
    unsigned bal = __ballot_sync(0xFFFFFFFFu, m);
    __shared__ int wcnt[8];
    if (lane == 0) wcnt[wid] = __popc(bal);
    __syncthreads();
    int woff = 0;
    for (int i = 0; i < wid; i++) woff += wcnt[i];
    if (m) {
        int pos = g_blkoff[blockIdx.x] + woff + __popc(bal & ((1u << lane) - 1));
        if (pos < MAXL) g_live[pos] = e;
    }
}

// ================= CSR scatter of compact indices by src node (grid-stride) =================
__global__ void csr_scatter_kernel(const int* __restrict__ src) {
    int nl = g_nlive;
    for (int c = blockIdx.x * 256 + threadIdx.x; c < nl; c += gridDim.x * 256) {
        int e = g_live[c];
        int p = atomicAdd(&g_cur[src[e]], 1);
        g_elist[p] = c;
    }
}

// ================= gather + split live ef rows =================
__global__ void gather_split_kernel(const float* __restrict__ ef) {
    int nl = g_nlive;
    size_t total = (size_t)nl * 128;
    size_t stride = (size_t)gridDim.x * blockDim.x;
    for (size_t id = (size_t)blockIdx.x * blockDim.x + threadIdx.x; id < total; id += stride) {
        int c = (int)(id >> 7), j = (int)(id & 127);
        int e = g_live[c];
        float4 x = reinterpret_cast<const float4*>(ef)[(size_t)e * 128 + j];
        __nv_bfloat162 h0 = __floats2bfloat162_rn(x.x, x.y);
        __nv_bfloat162 h1 = __floats2bfloat162_rn(x.z, x.w);
        uint2 hv, lv;
        hv.x = *reinterpret_cast<uint32_t*>(&h0);
        hv.y = *reinterpret_cast<uint32_t*>(&h1);
        lv.x = pack2bf(x.x - __bfloat162float(h0.x), x.y - __bfloat162float(h0.y));
        lv.y = pack2bf(x.z - __bfloat162float(h1.x), x.w - __bfloat162float(h1.y));
        reinterpret_cast<uint2*>(g_cefhi)[(size_t)c * 128 + j] = hv;
        reinterpret_cast<uint2*>(g_ceflo)[(size_t)c * 128 + j] = lv;
    }
}

// ================= generic fp32 -> bf16 hi/lo split =================
__global__ void split_kernel(const float* __restrict__ X, __nv_bfloat16* __restrict__ hi,
                             __nv_bfloat16* __restrict__ lo, size_t n4)
{
    size_t i = (size_t)blockIdx.x * blockDim.x + threadIdx.x;
    if (i >= n4) return;
    float4 x = reinterpret_cast<const float4*>(X)[i];
    __nv_bfloat162 h0 = __floats2bfloat162_rn(x.x, x.y);
    __nv_bfloat162 h1 = __floats2bfloat162_rn(x.z, x.w);
    uint2 hv, lv;
    hv.x = *reinterpret_cast<uint32_t*>(&h0);
    hv.y = *reinterpret_cast<uint32_t*>(&h1);
    lv.x = pack2bf(x.x - __bfloat162float(h0.x), x.y - __bfloat162float(h0.y));
    lv.y = pack2bf(x.z - __bfloat162float(h1.x), x.w - __bfloat162float(h1.y));
    reinterpret_cast<uint2*>(hi)[i] = hv;
    reinterpret_cast<uint2*>(lo)[i] = lv;
}

// ================= persistent mma.sync bf16-split GEMM (pre-split A & B) =================
// Row-block loop with stride gridDim.y*128 — no no-op CTAs.
// EPI 0: fp32 C + bias; EPI 4: split bf16 Chi/Clo; EPI 5: fused 3-output (sector by bn0>>9)
#define STAGE_BYTES 65536
#define GEMM_SMEM (3 * STAGE_BYTES)

template<int EPI>
__global__ __launch_bounds__(256, 1)
void mma_gemm(const __nv_bfloat16* __restrict__ Ahi, const __nv_bfloat16* __restrict__ Alo,
              const __nv_bfloat16* __restrict__ Bhi, const __nv_bfloat16* __restrict__ Blo,
              const float* __restrict__ bias, float* __restrict__ C,
              __nv_bfloat16* __restrict__ Chi, __nv_bfloat16* __restrict__ Clo,
              int Mstat, int K, const int* __restrict__ Mdyn,
              float* __restrict__ C1, float* __restrict__ C2,
              const float* __restrict__ bias1, const float* __restrict__ bias2)
{
    const int M = Mdyn ? *Mdyn : Mstat;
    extern __shared__ char sm[];
    const uint32_t sbase = (uint32_t)__cvta_generic_to_shared(sm);
    const int tid = threadIdx.x;
    const int w = tid >> 5, l = tid & 31;
    const int bn0 = blockIdx.x * 128;        // B row base (0..1535 for EPI 5)
    const int wm = w >> 2, wn = w & 3;

    float* Cout = C;
    const float* bptr = bias;
    int cn0 = bn0;
    if (EPI == 5) {
        int sec = bn0 >> 9;
        Cout = (sec == 0) ? C : (sec == 1 ? C1 : C2);
        bptr = (sec == 0) ? bias : (sec == 1 ? bias1 : bias2);
        cn0 = bn0 & 511;
    }
    const int nch = K >> 6;

    for (int row0 = blockIdx.y * 128; row0 < M; row0 += gridDim.y * 128) {
        __syncthreads();   // all smem readers from previous row-block done

        float acc[4][4][4];
        #pragma unroll
        for (int i = 0; i < 4; i++)
            #pragma unroll
            for (int j = 0; j < 4; j++)
                #pragma unroll
                for (int p = 0; p < 4; p++) acc[i][j][p] = 0.f;

        int srow[4];
        #pragma unroll
        for (int i = 0; i < 4; i++) {
            int r = row0 + (tid >> 3) + 32 * i;
            srow[i] = (r >= M) ? (M - 1) : r;
        }

        auto loadA = [&](int k0, int stage) {
            uint32_t sb = sbase + stage * STAGE_BYTES;
            #pragma unroll
            for (int i = 0; i < 4; i++) {
                int lin = tid + 256 * i;
                int r = lin >> 3, ch = lin & 7;
                uint32_t so = sb + r * 128 + (uint32_t)((ch ^ (r & 7)) * 16);
                size_t gi = (size_t)srow[i] * K + k0 + ch * 8;
                cpasync16(so, &Ahi[gi]);
                cpasync16(so + 16384, &Alo[gi]);
            }
        };
        auto loadB = [&](int k0, int stage) {
            uint32_t sb = sbase + stage * STAGE_BYTES + 32768;
            #pragma unroll
            for (int i = 0; i < 4; i++) {
                int lin = tid + 256 * i;
                int r = lin >> 3, ch = lin & 7;
                uint32_t so = sb + r * 128 + (uint32_t)((ch ^ (r & 7)) * 16);
                size_t gi = (size_t)(bn0 + r) * K + k0 + ch * 8;
                cpasync16(so, &Bhi[gi]);
                cpasync16(so + 16384, &Blo[gi]);
            }
        };
        auto compute = [&](int stage) {
            uint32_t ab = sbase + stage * STAGE_BYTES;
            uint32_t bb = ab + 32768;
            #pragma unroll
            for (int ks = 0; ks < 4; ks++) {
                int kc = ks * 2;
                uint32_t ahi[4][4], alo[4][4];
                #pragma unroll
                for (int mf = 0; mf < 4; mf++) {
                    int rr = wm * 64 + mf * 16 + (l & 15);
                    int kch = kc + (l >> 4);
                    uint32_t addr = ab + rr * 128 + (uint32_t)(((kch ^ (rr & 7))) * 16);
                    ldm4(ahi[mf], addr);
                    ldm4(alo[mf], addr + 16384);
                }
                uint32_t bhi[2][4], blo[2][4];
                #pragma unroll
                for (int ng = 0; ng < 2; ng++) {
                    int nr = wn * 32 + ng * 16 + (l & 7) + ((l >> 4) << 3);
                    int kch = kc + ((l >> 3) & 1);
                    uint32_t addr = bb + nr * 128 + (uint32_t)(((kch ^ (nr & 7))) * 16);
                    ldm4(bhi[ng], addr);
                    ldm4(blo[ng], addr + 16384);
                }
                #pragma unroll
                for (int mf = 0; mf < 4; mf++) {
                    #pragma unroll
                    for (int nf = 0; nf < 4; nf++) {
                        int ng = nf >> 1, sb2 = (nf & 1) * 2;
                        mma_bf16(acc[mf][nf], ahi[mf], bhi[ng][sb2], bhi[ng][sb2 + 1]);
                        mma_bf16(acc[mf][nf], ahi[mf], blo[ng][sb2], blo[ng][sb2 + 1]);
                        mma_bf16(acc[mf][nf], alo[mf], bhi[ng][sb2], bhi[ng][sb2 + 1]);
                    }
                }
            }
        };

        loadA(0, 0); loadB(0, 0); cp_commit();
        if (nch > 1) { loadA(64, 1); loadB(64, 1); cp_commit(); }
        else cp_commit();
        for (int c = 0; c < nch; c++) {
            __syncthreads();
            if (c + 2 < nch) { loadA((c + 2) * 64, (c + 2) % 3); loadB((c + 2) * 64, (c + 2) % 3); }
            cp_commit();
            CP_WAIT(2);
            __syncthreads();
            compute(c % 3);
        }

        #pragma unroll
        for (int mf = 0; mf < 4; mf++) {
            int gr0 = row0 + wm * 64 + mf * 16 + (l >> 2);
            #pragma unroll
            for (int nf = 0; nf < 4; nf++) {
                int gc = cn0 + wn * 32 + nf * 8 + (l & 3) * 2;
                float b0 = bptr[gc], b1 = bptr[gc + 1];
                #pragma unroll
                for (int h = 0; h < 2; h++) {
                    int grow = gr0 + 8 * h;
                    if (grow >= M) continue;
                    float v0 = acc[mf][nf][2 * h] + b0;
                    float v1 = acc[mf][nf][2 * h + 1] + b1;
                    if (EPI == 4) {
                        __nv_bfloat162 hh = __floats2bfloat162_rn(v0, v1);
                        uint32_t hw = *reinterpret_cast<uint32_t*>(&hh);
                        uint32_t lw = pack2bf(v0 - __bfloat162float(hh.x), v1 - __bfloat162float(hh.y));
                        *reinterpret_cast<uint32_t*>(&Chi[(size_t)grow * DE + gc]) = hw;
                        *reinterpret_cast<uint32_t*>(&Clo[(size_t)grow * DE + gc]) = lw;
                    } else {
                        *reinterpret_cast<float2*>(&Cout[(size_t)grow * DE + gc]) = make_float2(v0, v1);
                    }
                }
            }
        }
    }
}

// ================= qbk + live attention logits, merged (grid-stride, warp per item) =================
__global__ void attn_qbk_kernel(const int* __restrict__ src, const float* __restrict__ bk) {
    int nwarps = gridDim.x * 8;
    int warp0 = blockIdx.x * 8 + (threadIdx.x >> 5);
    int lane = threadIdx.x & 31;
    int total = NN + g_nlive;
    int base = lane * 4;
    for (int i = warp0; i < total; i += nwarps) {
        const float4 *qr, *kr;
        int c = i - NN;
        if (i < NN) {
            qr = reinterpret_cast<const float4*>(g_q + (size_t)i * DE);
            kr = reinterpret_cast<const float4*>(bk);
        } else {
            int e = g_live[c];
            qr = reinterpret_cast<const float4*>(g_q + (size_t)src[e] * DE);
            kr = reinterpret_cast<const float4*>(g_kc + (size_t)c * DE);
        }
        float s = 0.f;
        #pragma unroll
        for (int j = 0; j < 4; j++) {
            float4 a = qr[base + j], b = kr[base + j];
            s += a.x * b.x + a.y * b.y + a.z * b.z + a.w * b.w;
        }
        s += __shfl_xor_sync(0xFFFFFFFFu, s, 1);
        s += __shfl_xor_sync(0xFFFFFFFFu, s, 2);
        if ((lane & 3) == 0) {
            int h = lane >> 2;
            if (i < NN) g_qbk[(size_t)i * NH + h] = s * 0.125f;
            else        g_scc[(size_t)c * NH + h] = s * 0.125f;
        }
    }
}

// ================= segment softmax + aggregation (live + analytic dead) =================
__global__ void softmax_agg_kernel(const float* __restrict__ bv) {
    int n = blockIdx.x;
    int off = g_off[n];
    int degl = g_off[n + 1] - off;
    int ndead = g_degt[n] - degl;
    int tid = threadIdx.x;
    int wid = tid >> 5, lane = tid & 31;
    int d0 = tid * 2;

    if (degl + ndead == 0) {
        *reinterpret_cast<float2*>(g_agg + (size_t)n * DE + d0) = make_float2(0.f, 0.f);
        return;
    }
    __shared__ float m_sh[NH], d_sh[NH], cdead_sh[NH];
    __shared__ float attn_sh[64 * NH];
    {
        float qb = g_qbk[(size_t)n * NH + wid];
        float mx = -INFINITY;
        for (int i = lane; i < degl; i += 32) {
            int c = g_elist[off + i];
            mx = fmaxf(mx, g_scc[(size_t)c * NH + wid]);
        }
        #pragma unroll
        for (int o = 16; o; o >>= 1) mx = fmaxf(mx, __shfl_xor_sync(0xFFFFFFFFu, mx, o));
        if (ndead > 0) mx = fmaxf(mx, qb);
        float sm = 0.f;
        for (int i = lane; i < degl; i += 32) {
            int c = g_elist[off + i];
            sm += expf(g_scc[(size_t)c * NH + wid] - mx);
        }
        #pragma unroll
        for (int o = 16; o; o >>= 1) sm += __shfl_xor_sync(0xFFFFFFFFu, sm, o);
        if (lane == 0) {
            float dterm = (ndead > 0) ? (float)ndead * expf(qb - mx) : 0.f;
            float den = sm + dterm;
            m_sh[wid] = mx; d_sh[wid] = den; cdead_sh[wid] = dterm / den;
        }
    }
    __syncthreads();
    float2 acc = make_float2(0.f, 0.f);
    int h = d0 >> 6;
    for (int base = 0; base < degl; base += 64) {
        int cnt = min(64, degl - base);
        __syncthreads();
        for (int idx = tid; idx < cnt * NH; idx += 256) {
            int j = idx >> 3, hh = idx & 7;
            int c = g_elist[off + base + j];
            attn_sh[idx] = expf(g_scc[(size_t)c * NH + hh] - m_sh[hh]) / d_sh[hh];
        }
        __syncthreads();
        for (int j = 0; j < cnt; j++) {
            int c = g_elist[off + base + j];
            float a = attn_sh[j * NH + h];
            float2 vv = *reinterpret_cast<const float2*>(g_vc + (size_t)c * DE + d0);
            acc.x += a * vv.x;
            acc.y += a * vv.y;
        }
    }
    float cd = cdead_sh[h];
    acc.x += cd * bv[d0];
    acc.y += cd * bv[d0 + 1];
    *reinterpret_cast<float2*>(g_agg + (size_t)n * DE + d0) = acc;
}

// ================= merged outputs: per-node classifier + live-edge output =================
__global__ void out_kernel(const int* __restrict__ src, const float* __restrict__ W2,
                           const float* __restrict__ b2, float* __restrict__ out) {
    __shared__ float W2s[DE * NC];
    int tid = threadIdx.x;
    for (int i = tid; i < DE * NC; i += 256) W2s[i] = W2[i];
    __syncthreads();
    int nwarps = gridDim.x * 8;
    int lane = tid & 31;
    int total = NN + g_nlive;
    for (int i = blockIdx.x * 8 + (tid >> 5); i < total; i += nwarps) {
        const float* ntr;
        const float* fr = nullptr;
        float* dstp;
        if (i < NN) {
            ntr = g_nt + (size_t)i * DE;
            dstp = g_outc + (size_t)i * NC;
        } else {
            int c = i - NN;
            int e = g_live[c];
            ntr = g_nt + (size_t)src[e] * DE;
            fr = g_efw1 + (size_t)c * DE;
            dstp = out + (size_t)e * NC;
        }
        float p[NC];
        #pragma unroll
        for (int cc = 0; cc < NC; cc++) p[cc] = 0.f;
        for (int k = lane; k < DE; k += 32) {
            float hv = gelu_exact(fr ? (ntr[k] + fr[k]) : ntr[k]);
            const float* wk = &W2s[k * NC];
            #pragma unroll
            for (int cc = 0; cc < NC; cc++) p[cc] += hv * wk[cc];
        }
        #pragma unroll
        for (int cc = 0; cc < NC; cc++) {
            #pragma unroll
            for (int o = 16; o; o >>= 1) p[cc] += __shfl_xor_sync(0xFFFFFFFFu, p[cc], o);
        }
        if (lane == 0) {
            #pragma unroll
            for (int cc = 0; cc < NC; cc++) dstp[cc] = p[cc] + b2[cc];
        }
    }
}

// ================= dead-edge output: copy per-node classifier =================
__global__ void dead_out_kernel(const int* __restrict__ src, float* __restrict__ out) {
    int e = blockIdx.x * 256 + threadIdx.x;
    if (e >= EE || g_emask8[e]) return;
    const float* s = g_outc + (size_t)src[e] * NC;
    float* d = out + (size_t)e * NC;
    #pragma unroll
    for (int c = 0; c < NC; c++) d[c] = s[c];
}

// ================= host launcher =================
extern "C" void kernel_launch(void* const* d_in, const int* in_sizes, int n_in,
                              void* d_out, int out_size)
{
    const float* node_features = (const float*)d_in[0];
    const float* edge_features = (const float*)d_in[1];
    const int*   edge_index    = (const int*)d_in[2];
    const float* nw = (const float*)d_in[4];
    const float* nb = (const float*)d_in[5];
    const float* ew = (const float*)d_in[6];
    const float* eb = (const float*)d_in[7];
    const float* Wq = (const float*)d_in[8];  const float* bq = (const float*)d_in[9];
    const float* Wk = (const float*)d_in[10]; const float* bk = (const float*)d_in[11];
    const float* Wv = (const float*)d_in[12]; const float* bv = (const float*)d_in[13];
    const float* Wo = (const float*)d_in[14]; const float* bo = (const float*)d_in[15];
    const float* W1 = (const float*)d_in[16]; const float* b1 = (const float*)d_in[17];
    const float* W2 = (const float*)d_in[18]; const float* b2 = (const float*)d_in[19];
    float* out = (float*)d_out;
    const int* src = edge_index;
    const int* dst = edge_index + EE;

    float *qp, *kcp, *vcp, *efw1p, *aggp, *ntp, *zbp;
    __nv_bfloat16 *whi, *wlo, *cefhi, *ceflo, *nfhi, *nflo, *aghi, *aglo, *awhi, *awlo;
    int *nlp;
    cudaGetSymbolAddress((void**)&qp,    g_q);
    cudaGetSymbolAddress((void**)&kcp,   g_kc);
    cudaGetSymbolAddress((void**)&vcp,   g_vc);
    cudaGetSymbolAddress((void**)&efw1p, g_efw1);
    cudaGetSymbolAddress((void**)&aggp,  g_agg);
    cudaGetSymbolAddress((void**)&ntp,   g_nt);
    cudaGetSymbolAddress((void**)&zbp,   g_zb);
    cudaGetSymbolAddress((void**)&whi,   g_whi);
    cudaGetSymbolAddress((void**)&wlo,   g_wlo);
    cudaGetSymbolAddress((void**)&cefhi, g_cefhi);
    cudaGetSymbolAddress((void**)&ceflo, g_ceflo);
    cudaGetSymbolAddress((void**)&nfhi,  g_nfhi);
    cudaGetSymbolAddress((void**)&nflo,  g_nflo);
    cudaGetSymbolAddress((void**)&aghi,  g_agghi);
    cudaGetSymbolAddress((void**)&aglo,  g_agglo);
    cudaGetSymbolAddress((void**)&awhi,  g_awhi);
    cudaGetSymbolAddress((void**)&awlo,  g_awlo);
    cudaGetSymbolAddress((void**)&nlp,   g_nlive);

    cudaFuncSetAttribute((const void*)mma_gemm<0>, cudaFuncAttributeMaxDynamicSharedMemorySize, GEMM_SMEM);
    cudaFuncSetAttribute((const void*)mma_gemm<4>, cudaFuncAttributeMaxDynamicSharedMemorySize, GEMM_SMEM);
    cudaFuncSetAttribute((const void*)mma_gemm<5>, cudaFuncAttributeMaxDynamicSharedMemorySize, GEMM_SMEM);

    const size_t SB = (size_t)DE * DE;
    const int PREP_BLOCKS = (DE * DN + 4 * DE * DE + NN * DN / 4 + NN + 255) / 256;

    // 0. fused prep: weight splits + node-feature split + zeroing
    prep_kernel<<<PREP_BLOCKS, 256>>>(Wq, Wk, Wv, W1, Wo, node_features);

    // 1. both exact fp32 scorers in one launch
    score_all_kernel<<<(NN + EE + 7) / 8, 256>>>(node_features, edge_features, nw, nb, ew, eb);

    // 2. both top-k thresholds
    topk_kernel<<<2, 1024>>>();

    // 3-5. mask + counts, scans, compaction, CSR (grid-stride)
    emask_count_kernel<<<625, 256>>>(src, dst);
    scan2_kernel<<<1, 1024>>>();
    compact_kernel<<<625, 256>>>();
    csr_scatter_kernel<<<296, 256>>>(src);

    // 6. gather + split live ef rows
    gather_split_kernel<<<1024, 256>>>(edge_features);

    // 7. GEMMs (persistent row-block loops — no no-op CTAs)
    mma_gemm<0><<<dim3(4, 37), 256, GEMM_SMEM>>>(nfhi, nflo, whi + 0 * SB, wlo + 0 * SB, bq,
                                        qp, nullptr, nullptr, NN, DN, nullptr,
                                        nullptr, nullptr, nullptr, nullptr);
    // fused k|v|efW1: one N=1536 GEMM over contiguous Wk|Wv|W1 (slots 1..3)
    mma_gemm<5><<<dim3(12, 12), 256, GEMM_SMEM>>>(cefhi, ceflo, whi + 1 * SB, wlo + 1 * SB, bk,
                                        kcp, nullptr, nullptr, 0, DE, nlp,
                                        vcp, efw1p, bv, zbp);

    // 8. attention: qbk + live logits merged, then segment softmax + aggregation
    attn_qbk_kernel<<<592, 256>>>(src, bk);
    softmax_agg_kernel<<<NN, 256>>>(bv);

    // 9. node-side chain: agg -> aggWo (slot 4, split out) -> nodeterm (slot 3 = W1)
    split_kernel<<<((size_t)NN * DE / 4 + 255) / 256, 256>>>(aggp, aghi, aglo, (size_t)NN * DE / 4);
    mma_gemm<4><<<dim3(4, 37), 256, GEMM_SMEM>>>(aghi, aglo, whi + 4 * SB, wlo + 4 * SB, bo,
                                        nullptr, awhi, awlo, NN, DE, nullptr,
                                        nullptr, nullptr, nullptr, nullptr);
    mma_gemm<0><<<dim3(4, 37), 256, GEMM_SMEM>>>(awhi, awlo, whi + 3 * SB, wlo + 3 * SB, b1,
                                        ntp, nullptr, nullptr, NN, DE, nullptr,
                                        nullptr, nullptr, nullptr, nullptr);

    // 10. outputs: node classifier + live edges merged, then dead-edge copy
    out_kernel<<<592, 256>>>(src, W2, b2, out);
    dead_out_kernel<<<625, 256>>>(src, out);
}

// round 11
// speedup vs baseline: 1.0755x; 1.0755x over previous
#include <cuda_runtime.h>
#include <cuda_bf16.h>
#include <math.h>
#include <stdint.h>

// ---------------- problem constants ----------------
#define NN 10000
#define EE 160000
#define DN 256
#define DE 512
#define NH 8
#define NC 10
#define KN 5000
#define KE 80000
#define MAXL 80000   // worst-case live edges

// ---------------- device scratch ----------------
__device__ float g_q[(size_t)NN * DE];
__device__ float g_kc[(size_t)MAXL * DE];
__device__ float g_vc[(size_t)MAXL * DE];
__device__ float g_efw1[(size_t)MAXL * DE];
__device__ float g_scc[(size_t)MAXL * NH];
__device__ float g_qbk[(size_t)NN * NH];
__device__ float g_agg[(size_t)NN * DE];
__device__ float g_nt[(size_t)NN * DE];
__device__ float g_outc[(size_t)NN * NC];
__device__ float g_nscore[NN];
__device__ float g_escore[EE];
__device__ unsigned char g_emask8[EE];
__device__ float g_thr[2];
__device__ float g_zb[DE];
// bf16 hi/lo splits
__device__ __nv_bfloat16 g_cefhi[(size_t)MAXL * DE];
__device__ __nv_bfloat16 g_ceflo[(size_t)MAXL * DE];
__device__ __nv_bfloat16 g_nfhi[(size_t)NN * DN];
__device__ __nv_bfloat16 g_nflo[(size_t)NN * DN];
__device__ __nv_bfloat16 g_agghi[(size_t)NN * DE];
__device__ __nv_bfloat16 g_agglo[(size_t)NN * DE];
__device__ __nv_bfloat16 g_awhi[(size_t)NN * DE];
__device__ __nv_bfloat16 g_awlo[(size_t)NN * DE];
// weights: slot 0=Wq(K=256), 1=Wk, 2=Wv, 3=Wo, 4=W1  ([Nout=512, K] K-major)
__device__ __nv_bfloat16 g_whi[5][DE * DE];
__device__ __nv_bfloat16 g_wlo[5][DE * DE];
// compaction / CSR
__device__ int g_live[MAXL];
__device__ int g_blkcnt[625];
__device__ int g_blkoff[625];
__device__ int g_nlive;
__device__ int g_degt[NN];
__device__ int g_degl[NN];
__device__ int g_off[NN + 1];
__device__ int g_cur[NN];
__device__ int g_elist[MAXL];

// ================= PTX helpers =================
__device__ __forceinline__ void ldm4(uint32_t* r, uint32_t a) {
    asm volatile("ldmatrix.sync.aligned.m8n8.x4.shared.b16 {%0,%1,%2,%3}, [%4];"
                 : "=r"(r[0]), "=r"(r[1]), "=r"(r[2]), "=r"(r[3]) : "r"(a));
}
__device__ __forceinline__ void mma_bf16(float* d, const uint32_t* a, uint32_t b0, uint32_t b1) {
    asm volatile("mma.sync.aligned.m16n8k16.row.col.f32.bf16.bf16.f32 "
                 "{%0,%1,%2,%3},{%4,%5,%6,%7},{%8,%9},{%0,%1,%2,%3};"
                 : "+f"(d[0]), "+f"(d[1]), "+f"(d[2]), "+f"(d[3])
                 : "r"(a[0]), "r"(a[1]), "r"(a[2]), "r"(a[3]), "r"(b0), "r"(b1));
}
__device__ __forceinline__ void cpasync16(uint32_t s, const void* g) {
    asm volatile("cp.async.cg.shared.global [%0], [%1], 16;" :: "r"(s), "l"(g));
}
__device__ __forceinline__ void cp_commit() { asm volatile("cp.async.commit_group;" ::: "memory"); }
#define CP_WAIT(n) asm volatile("cp.async.wait_group %0;" :: "n"(n) : "memory")

__device__ __forceinline__ uint32_t pack2bf(float x, float y) {
    __nv_bfloat162 h = __floats2bfloat162_rn(x, y);
    return *reinterpret_cast<uint32_t*>(&h);
}
__device__ __forceinline__ float gelu_exact(float x) {
    return 0.5f * x * (1.0f + erff(x * 0.70710678118654752f));
}

// ================= scorers: one warp per row =================
__global__ void score_kernel(const float* __restrict__ X, const float* __restrict__ w,
                             const float* __restrict__ b, float* __restrict__ out,
                             int M, int K)
{
    int warp = (blockIdx.x * blockDim.x + threadIdx.x) >> 5;
    int lane = threadIdx.x & 31;
    if (warp >= M) return;
    const float* row = X + (size_t)warp * K;
    float s = 0.f;
    for (int k = lane; k < K; k += 32) s += row[k] * w[k];
    #pragma unroll
    for (int o = 16; o; o >>= 1) s += __shfl_xor_sync(0xFFFFFFFFu, s, o);
    if (lane == 0) out[warp] = s + b[0];
}

// ================= zero init =================
__global__ void zero_kernel() {
    int i = blockIdx.x * blockDim.x + threadIdx.x;
    if (i < NN) { g_degt[i] = 0; g_degl[i] = 0; }
    if (i < DE) g_zb[i] = 0.f;
}

// ================= dual top-k (exact 4x8-bit radix; warp-aggregated atomics) =================
__device__ __forceinline__ unsigned f2u_ord(float x) {
    unsigned u = __float_as_uint(x);
    return (u & 0x80000000u) ? ~u : (u | 0x80000000u);
}
__global__ void topk_kernel() {
    int b = blockIdx.x;                       // 0: nodes, 1: edges
    const float* data = b ? g_escore : g_nscore;
    int n = b ? EE : NN;
    unsigned k = b ? KE : KN;
    __shared__ unsigned hist[256];
    __shared__ unsigned prefix_s, krem_s;
    int tid = threadIdx.x;
    int lane = tid & 31;
    if (tid == 0) { prefix_s = 0u; krem_s = k; }
    __syncthreads();
    int nIter = (n + blockDim.x - 1) / blockDim.x;
    for (int shift = 24; shift >= 0; shift -= 8) {
        if (tid < 256) hist[tid] = 0u;
        __syncthreads();
        unsigned prefix = prefix_s;
        unsigned maskhi = (shift == 24) ? 0u : (0xFFFFFFFFu << (shift + 8));
        for (int it = 0; it < nIter; it++) {
            int i = it * blockDim.x + tid;
            bool ok = false; unsigned dig = 0;
            if (i < n) {
                unsigned u = f2u_ord(data[i]);
                ok = ((u & maskhi) == prefix);
                dig = (u >> shift) & 255u;
            }
            unsigned key = ok ? dig : 0xFFFFFFFFu;
            unsigned grp = __match_any_sync(0xFFFFFFFFu, key);
            if (ok && lane == (__ffs(grp) - 1))
                atomicAdd(&hist[dig], (unsigned)__popc(grp));
        }
        __syncthreads();
        if (tid == 0) {
            unsigned krem = krem_s, cum = 0; int digit = 0;
            for (int d = 255; d >= 0; d--) {
                unsigned c = hist[d];
                if (cum + c >= krem) { digit = d; break; }
                cum += c;
            }
            prefix_s |= ((unsigned)digit) << shift;
            krem_s = krem - cum;
        }
        __syncthreads();
    }
    if (tid == 0) {
        unsigned u = prefix_s;
        u = (u & 0x80000000u) ? (u & 0x7FFFFFFFu) : ~u;
        g_thr[b] = __uint_as_float(u);
    }
}

// ================= edge mask + degree counts + per-block live counts =================
__global__ void emask_count_kernel(const int* __restrict__ src, const int* __restrict__ dst) {
    int e = blockIdx.x * 256 + threadIdx.x;
    bool live = false;
    if (e < EE) {
        float tn = g_thr[0], te = g_thr[1];
        live = (g_escore[e] >= te) && (g_nscore[src[e]] >= tn) && (g_nscore[dst[e]] >= tn);
        g_emask8[e] = live ? 1 : 0;
        atomicAdd(&g_degt[src[e]], 1);
        if (live) atomicAdd(&g_degl[src[e]], 1);
    }
    int cnt = __syncthreads_count(live);
    if (threadIdx.x == 0) g_blkcnt[blockIdx.x] = cnt;
}

// ================= scans =================
__global__ void scan2_kernel() {   // 1 block, 1024 threads
    int t = threadIdx.x;
    if (t == 0) {
        int run = 0;
        for (int i = 0; i < 625; i++) { g_blkoff[i] = run; run += g_blkcnt[i]; }
        g_nlive = run > MAXL ? MAXL : run;
    }
    __syncthreads();
    __shared__ int part[1024];
    const int CH = (NN + 1023) / 1024;
    int s = 0;
    for (int j = 0; j < CH; j++) { int i = t * CH + j; if (i < NN) s += g_degl[i]; }
    part[t] = s;
    __syncthreads();
    if (t == 0) {
        int run = 0;
        for (int i = 0; i < 1024; i++) { int v = part[i]; part[i] = run; run += v; }
        g_off[NN] = run;
    }
    __syncthreads();
    int run = part[t];
    for (int j = 0; j < CH; j++) {
        int i = t * CH + j;
        if (i < NN) { g_off[i] = run; g_cur[i] = run; run += g_degl[i]; }
    }
}

// ================= deterministic order-preserving compaction =================
__global__ void compact_kernel() {
    int e = blockIdx.x * 256 + threadIdx.x;
    bool m = (e < EE) && g_emask8[e];
    int wid = threadIdx.x >> 5, lane = threadIdx.x & 31;
    unsigned bal = __ballot_sync(0xFFFFFFFFu, m);
    __shared__ int wcnt[8];
    if (lane == 0) wcnt[wid] = __popc(bal);
    __syncthreads();
    int woff = 0;
    for (int i = 0; i < wid; i++) woff += wcnt[i];
    if (m) {
        int pos = g_blkoff[blockIdx.x] + woff + __popc(bal & ((1u << lane) - 1));
        if (pos < MAXL) g_live[pos] = e;
    }
}

// ================= CSR scatter of compact indices by src node =================
__global__ void csr_scatter_kernel(const int* __restrict__ src) {
    int c = blockIdx.x * 256 + threadIdx.x;
    if (c < g_nlive) {
        int e = g_live[c];
        int p = atomicAdd(&g_cur[src[e]], 1);
        g_elist[p] = c;
    }
}

// ================= gather + split live ef rows =================
__global__ void gather_split_kernel(const float* __restrict__ ef) {
    int nl = g_nlive;
    size_t total = (size_t)nl * 128;
    size_t stride = (size_t)gridDim.x * blockDim.x;
    for (size_t id = (size_t)blockIdx.x * blockDim.x + threadIdx.x; id < total; id += stride) {
        int c = (int)(id >> 7), j = (int)(id & 127);
        int e = g_live[c];
        float4 x = reinterpret_cast<const float4*>(ef)[(size_t)e * 128 + j];
        __nv_bfloat162 h0 = __floats2bfloat162_rn(x.x, x.y);
        __nv_bfloat162 h1 = __floats2bfloat162_rn(x.z, x.w);
        uint2 hv, lv;
        hv.x = *reinterpret_cast<uint32_t*>(&h0);
        hv.y = *reinterpret_cast<uint32_t*>(&h1);
        lv.x = pack2bf(x.x - __bfloat162float(h0.x), x.y - __bfloat162float(h0.y));
        lv.y = pack2bf(x.z - __bfloat162float(h1.x), x.w - __bfloat162float(h1.y));
        reinterpret_cast<uint2*>(g_cefhi)[(size_t)c * 128 + j] = hv;
        reinterpret_cast<uint2*>(g_ceflo)[(size_t)c * 128 + j] = lv;
    }
}

// ================= generic fp32 -> bf16 hi/lo split =================
__global__ void split_kernel(const float* __restrict__ X, __nv_bfloat16* __restrict__ hi,
                             __nv_bfloat16* __restrict__ lo, size_t n4)
{
    size_t i = (size_t)blockIdx.x * blockDim.x + threadIdx.x;
    if (i >= n4) return;
    float4 x = reinterpret_cast<const float4*>(X)[i];
    __nv_bfloat162 h0 = __floats2bfloat162_rn(x.x, x.y);
    __nv_bfloat162 h1 = __floats2bfloat162_rn(x.z, x.w);
    uint2 hv, lv;
    hv.x = *reinterpret_cast<uint32_t*>(&h0);
    hv.y = *reinterpret_cast<uint32_t*>(&h1);
    lv.x = pack2bf(x.x - __bfloat162float(h0.x), x.y - __bfloat162float(h0.y));
    lv.y = pack2bf(x.z - __bfloat162float(h1.x), x.w - __bfloat162float(h1.y));
    reinterpret_cast<uint2*>(hi)[i] = hv;
    reinterpret_cast<uint2*>(lo)[i] = lv;
}

// ================= all 5 weight transposes + splits =================
// slots: 0=Wq(K=256), 1=Wk, 2=Wv, 3=Wo, 4=W1
__global__ void wconv_all(const float* __restrict__ Wq, const float* __restrict__ Wk,
                          const float* __restrict__ Wv, const float* __restrict__ Wo,
                          const float* __restrict__ W1)
{
    int idx = blockIdx.x * 256 + threadIdx.x;
    const int S0 = DE * DN;
    const int SB = DE * DE;
    int slot, K, r;
    const float* W;
    if (idx < S0) { slot = 0; K = DN; r = idx; W = Wq; }
    else {
        int t = idx - S0;
        slot = 1 + t / SB;
        if (slot > 4) return;
        r = t % SB; K = DE;
        W = (slot == 1) ? Wk : (slot == 2) ? Wv : (slot == 3) ? Wo : W1;
    }
    int n = r % DE, k = r / DE;
    float x = W[(size_t)k * DE + n];
    __nv_bfloat16 h = __float2bfloat16(x);
    g_whi[slot][n * K + k] = h;
    g_wlo[slot][n * K + k] = __float2bfloat16(x - __bfloat162float(h));
}

// ================= mma.sync bf16-split GEMM (pre-split A & B) =================
// C[M,512] = A[M,K] @ W^T + bias ; EPI 0: fp32 C ; EPI 4: split bf16 Chi/Clo
#define STAGE_BYTES 65536
#define GEMM_SMEM (3 * STAGE_BYTES)

template<int EPI>
__global__ __launch_bounds__(256, 1)
void mma_gemm(const __nv_bfloat16* __restrict__ Ahi, const __nv_bfloat16* __restrict__ Alo,
              const __nv_bfloat16* __restrict__ Bhi, const __nv_bfloat16* __restrict__ Blo,
              const float* __restrict__ bias, float* __restrict__ C,
              __nv_bfloat16* __restrict__ Chi, __nv_bfloat16* __restrict__ Clo,
              int Mstat, int K, const int* __restrict__ Mdyn)
{
    const int M = Mdyn ? *Mdyn : Mstat;
    const int row0 = blockIdx.y * 128;
    if (row0 >= M) return;
    extern __shared__ char sm[];
    const uint32_t sbase = (uint32_t)__cvta_generic_to_shared(sm);
    const int tid = threadIdx.x;
    const int w = tid >> 5, l = tid & 31;
    const int n0 = blockIdx.x * 128;
    const int wm = w >> 2, wn = w & 3;

    float acc[4][4][4];
    #pragma unroll
    for (int i = 0; i < 4; i++)
        #pragma unroll
        for (int j = 0; j < 4; j++)
            #pragma unroll
            for (int p = 0; p < 4; p++) acc[i][j][p] = 0.f;

    int srow[4];
    #pragma unroll
    for (int i = 0; i < 4; i++) {
        int r = row0 + (tid >> 3) + 32 * i;
        srow[i] = (r >= M) ? (M - 1) : r;
    }

    auto loadA = [&](int k0, int stage) {
        uint32_t sb = sbase + stage * STAGE_BYTES;
        #pragma unroll
        for (int i = 0; i < 4; i++) {
            int lin = tid + 256 * i;
            int r = lin >> 3, ch = lin & 7;
            uint32_t so = sb + r * 128 + (uint32_t)((ch ^ (r & 7)) * 16);
            size_t gi = (size_t)srow[i] * K + k0 + ch * 8;
            cpasync16(so, &Ahi[gi]);
            cpasync16(so + 16384, &Alo[gi]);
        }
    };
    auto loadB = [&](int k0, int stage) {
        uint32_t sb = sbase + stage * STAGE_BYTES + 32768;
        #pragma unroll
        for (int i = 0; i < 4; i++) {
            int lin = tid + 256 * i;
            int r = lin >> 3, ch = lin & 7;
            uint32_t so = sb + r * 128 + (uint32_t)((ch ^ (r & 7)) * 16);
            size_t gi = (size_t)(n0 + r) * K + k0 + ch * 8;
            cpasync16(so, &Bhi[gi]);
            cpasync16(so + 16384, &Blo[gi]);
        }
    };
    auto compute = [&](int stage) {
        uint32_t ab = sbase + stage * STAGE_BYTES;
        uint32_t bb = ab + 32768;
        #pragma unroll
        for (int ks = 0; ks < 4; ks++) {
            int kc = ks * 2;
            uint32_t ahi[4][4], alo[4][4];
            #pragma unroll
            for (int mf = 0; mf < 4; mf++) {
                int rr = wm * 64 + mf * 16 + (l & 15);
                int kch = kc + (l >> 4);
                uint32_t addr = ab + rr * 128 + (uint32_t)(((kch ^ (rr & 7))) * 16);
                ldm4(ahi[mf], addr);
                ldm4(alo[mf], addr + 16384);
            }
            uint32_t bhi[2][4], blo[2][4];
            #pragma unroll
            for (int ng = 0; ng < 2; ng++) {
                int nr = wn * 32 + ng * 16 + (l & 7) + ((l >> 4) << 3);
                int kch = kc + ((l >> 3) & 1);
                uint32_t addr = bb + nr * 128 + (uint32_t)(((kch ^ (nr & 7))) * 16);
                ldm4(bhi[ng], addr);
                ldm4(blo[ng], addr + 16384);
            }
            #pragma unroll
            for (int mf = 0; mf < 4; mf++) {
                #pragma unroll
                for (int nf = 0; nf < 4; nf++) {
                    int ng = nf >> 1, sb2 = (nf & 1) * 2;
                    mma_bf16(acc[mf][nf], ahi[mf], bhi[ng][sb2], bhi[ng][sb2 + 1]);
                    mma_bf16(acc[mf][nf], ahi[mf], blo[ng][sb2], blo[ng][sb2 + 1]);
                    mma_bf16(acc[mf][nf], alo[mf], bhi[ng][sb2], bhi[ng][sb2 + 1]);
                }
            }
        }
    };

    const int nch = K >> 6;
    loadA(0, 0); loadB(0, 0); cp_commit();
    if (nch > 1) { loadA(64, 1); loadB(64, 1); cp_commit(); }
    else cp_commit();
    for (int c = 0; c < nch; c++) {
        __syncthreads();
        if (c + 2 < nch) { loadA((c + 2) * 64, (c + 2) % 3); loadB((c + 2) * 64, (c + 2) % 3); }
        cp_commit();
        CP_WAIT(2);
        __syncthreads();
        compute(c % 3);
    }

    #pragma unroll
    for (int mf = 0; mf < 4; mf++) {
        int gr0 = row0 + wm * 64 + mf * 16 + (l >> 2);
        #pragma unroll
        for (int nf = 0; nf < 4; nf++) {
            int gc = n0 + wn * 32 + nf * 8 + (l & 3) * 2;
            float b0 = bias[gc], b1 = bias[gc + 1];
            #pragma unroll
            for (int h = 0; h < 2; h++) {
                int grow = gr0 + 8 * h;
                if (grow >= M) continue;
                float v0 = acc[mf][nf][2 * h] + b0;
                float v1 = acc[mf][nf][2 * h + 1] + b1;
                if (EPI == 4) {
                    __nv_bfloat162 hh = __floats2bfloat162_rn(v0, v1);
                    uint32_t hw = *reinterpret_cast<uint32_t*>(&hh);
                    uint32_t lw = pack2bf(v0 - __bfloat162float(hh.x), v1 - __bfloat162float(hh.y));
                    *reinterpret_cast<uint32_t*>(&Chi[(size_t)grow * DE + gc]) = hw;
                    *reinterpret_cast<uint32_t*>(&Clo[(size_t)grow * DE + gc]) = lw;
                } else {
                    *reinterpret_cast<float2*>(&C[(size_t)grow * DE + gc]) = make_float2(v0, v1);
                }
            }
        }
    }
}

// ================= qbk: dead-edge logit per node/head =================
__global__ void qbk_kernel(const float* __restrict__ bk) {
    int n = blockIdx.x * 8 + (threadIdx.x >> 5);
    int lane = threadIdx.x & 31;
    if (n >= NN) return;
    const float4* qr = reinterpret_cast<const float4*>(g_q + (size_t)n * DE);
    const float4* br = reinterpret_cast<const float4*>(bk);
    float s = 0.f;
    int base = lane * 4;
    #pragma unroll
    for (int j = 0; j < 4; j++) {
        float4 a = qr[base + j], b = br[base + j];
        s += a.x * b.x + a.y * b.y + a.z * b.z + a.w * b.w;
    }
    s += __shfl_xor_sync(0xFFFFFFFFu, s, 1);
    s += __shfl_xor_sync(0xFFFFFFFFu, s, 2);
    if ((lane & 3) == 0) g_qbk[(size_t)n * NH + (lane >> 2)] = s * 0.125f;
}

// ================= attention logits: one warp per live edge =================
__global__ void attn_live_kernel(const int* __restrict__ src) {
    int c = blockIdx.x * 8 + (threadIdx.x >> 5);
    int lane = threadIdx.x & 31;
    if (c >= g_nlive) return;
    int e = g_live[c];
    const float4* qr = reinterpret_cast<const float4*>(g_q + (size_t)src[e] * DE);
    const float4* kr = reinterpret_cast<const float4*>(g_kc + (size_t)c * DE);
    float s = 0.f;
    int base = lane * 4;
    #pragma unroll
    for (int j = 0; j < 4; j++) {
        float4 a = qr[base + j], b = kr[base + j];
        s += a.x * b.x + a.y * b.y + a.z * b.z + a.w * b.w;
    }
    s += __shfl_xor_sync(0xFFFFFFFFu, s, 1);
    s += __shfl_xor_sync(0xFFFFFFFFu, s, 2);
    if ((lane & 3) == 0) g_scc[(size_t)c * NH + (lane >> 2)] = s * 0.125f;
}

// ================= segment softmax + aggregation (live + analytic dead) =================
__global__ void softmax_agg_kernel(const float* __restrict__ bv) {
    int n = blockIdx.x;
    int off = g_off[n];
    int degl = g_off[n + 1] - off;
    int ndead = g_degt[n] - degl;
    int tid = threadIdx.x;
    int wid = tid >> 5, lane = tid & 31;
    int d0 = tid * 2;

    if (degl + ndead == 0) {
        *reinterpret_cast<float2*>(g_agg + (size_t)n * DE + d0) = make_float2(0.f, 0.f);
        return;
    }
    __shared__ float m_sh[NH], d_sh[NH], cdead_sh[NH];
    __shared__ float attn_sh[64 * NH];
    {
        float qb = g_qbk[(size_t)n * NH + wid];
        float mx = -INFINITY;
        for (int i = lane; i < degl; i += 32) {
            int c = g_elist[off + i];
            mx = fmaxf(mx, g_scc[(size_t)c * NH + wid]);
        }
        #pragma unroll
        for (int o = 16; o; o >>= 1) mx = fmaxf(mx, __shfl_xor_sync(0xFFFFFFFFu, mx, o));
        if (ndead > 0) mx = fmaxf(mx, qb);
        float sm = 0.f;
        for (int i = lane; i < degl; i += 32) {
            int c = g_elist[off + i];
            sm += expf(g_scc[(size_t)c * NH + wid] - mx);
        }
        #pragma unroll
        for (int o = 16; o; o >>= 1) sm += __shfl_xor_sync(0xFFFFFFFFu, sm, o);
        if (lane == 0) {
            float dterm = (ndead > 0) ? (float)ndead * expf(qb - mx) : 0.f;
            float den = sm + dterm;
            m_sh[wid] = mx; d_sh[wid] = den; cdead_sh[wid] = dterm / den;
        }
    }
    __syncthreads();
    float2 acc = make_float2(0.f, 0.f);
    int h = d0 >> 6;
    for (int base = 0; base < degl; base += 64) {
        int cnt = min(64, degl - base);
        __syncthreads();
        for (int idx = tid; idx < cnt * NH; idx += 256) {
            int j = idx >> 3, hh = idx & 7;
            int c = g_elist[off + base + j];
            attn_sh[idx] = expf(g_scc[(size_t)c * NH + hh] - m_sh[hh]) / d_sh[hh];
        }
        __syncthreads();
        for (int j = 0; j < cnt; j++) {
            int c = g_elist[off + base + j];
            float a = attn_sh[j * NH + h];
            float2 vv = *reinterpret_cast<const float2*>(g_vc + (size_t)c * DE + d0);
            acc.x += a * vv.x;
            acc.y += a * vv.y;
        }
    }
    float cd = cdead_sh[h];
    acc.x += cd * bv[d0];
    acc.y += cd * bv[d0 + 1];
    *reinterpret_cast<float2*>(g_agg + (size_t)n * DE + d0) = acc;
}

// ================= per-node classifier (dead-edge output) =================
__global__ void classify_node_kernel(const float* __restrict__ W2, const float* __restrict__ b2) {
    __shared__ float W2s[DE * NC];
    int tid = threadIdx.x;
    for (int i = tid; i < DE * NC; i += 256) W2s[i] = W2[i];
    __syncthreads();
    int n = blockIdx.x * 8 + (tid >> 5);
    if (n >= NN) return;
    int lane = tid & 31;
    const float* ntr = g_nt + (size_t)n * DE;
    float p[NC];
    #pragma unroll
    for (int c = 0; c < NC; c++) p[c] = 0.f;
    for (int k = lane; k < DE; k += 32) {
        float hv = gelu_exact(ntr[k]);
        const float* wk = &W2s[k * NC];
        #pragma unroll
        for (int c = 0; c < NC; c++) p[c] += hv * wk[c];
    }
    #pragma unroll
    for (int c = 0; c < NC; c++) {
        #pragma unroll
        for (int o = 16; o; o >>= 1) p[c] += __shfl_xor_sync(0xFFFFFFFFu, p[c], o);
    }
    if (lane == 0) {
        #pragma unroll
        for (int c = 0; c < NC; c++) g_outc[(size_t)n * NC + c] = p[c] + b2[c];
    }
}

// ================= live-edge output: gelu(nt[src]+efW1) @ W2 =================
__global__ void live_out_kernel(const int* __restrict__ src, const float* __restrict__ W2,
                                const float* __restrict__ b2, float* __restrict__ out) {
    __shared__ float W2s[DE * NC];
    int tid = threadIdx.x;
    for (int i = tid; i < DE * NC; i += 256) W2s[i] = W2[i];
    __syncthreads();
    int c = blockIdx.x * 8 + (tid >> 5);
    if (c >= g_nlive) return;
    int e = g_live[c];
    int lane = tid & 31;
    const float* ntr = g_nt + (size_t)src[e] * DE;
    const float* fr = g_efw1 + (size_t)c * DE;
    float p[NC];
    #pragma unroll
    for (int cc = 0; cc < NC; cc++) p[cc] = 0.f;
    for (int k = lane; k < DE; k += 32) {
        float hv = gelu_exact(ntr[k] + fr[k]);
        const float* wk = &W2s[k * NC];
        #pragma unroll
        for (int cc = 0; cc < NC; cc++) p[cc] += hv * wk[cc];
    }
    #pragma unroll
    for (int cc = 0; cc < NC; cc++) {
        #pragma unroll
        for (int o = 16; o; o >>= 1) p[cc] += __shfl_xor_sync(0xFFFFFFFFu, p[cc], o);
    }
    if (lane == 0) {
        #pragma unroll
        for (int cc = 0; cc < NC; cc++) out[(size_t)e * NC + cc] = p[cc] + b2[cc];
    }
}

// ================= dead-edge output: copy per-node classifier =================
__global__ void dead_out_kernel(const int* __restrict__ src, float* __restrict__ out) {
    int e = blockIdx.x * 256 + threadIdx.x;
    if (e >= EE || g_emask8[e]) return;
    const float* s = g_outc + (size_t)src[e] * NC;
    float* d = out + (size_t)e * NC;
    #pragma unroll
    for (int c = 0; c < NC; c++) d[c] = s[c];
}

// ================= host launcher =================
extern "C" void kernel_launch(void* const* d_in, const int* in_sizes, int n_in,
                              void* d_out, int out_size)
{
    const float* node_features = (const float*)d_in[0];
    const float* edge_features = (const float*)d_in[1];
    const int*   edge_index    = (const int*)d_in[2];
    const float* nw = (const float*)d_in[4];
    const float* nb = (const float*)d_in[5];
    const float* ew = (const float*)d_in[6];
    const float* eb = (const float*)d_in[7];
    const float* Wq = (const float*)d_in[8];  const float* bq = (const float*)d_in[9];
    const float* Wk = (const float*)d_in[10]; const float* bk = (const float*)d_in[11];
    const float* Wv = (const float*)d_in[12]; const float* bv = (const float*)d_in[13];
    const float* Wo = (const float*)d_in[14]; const float* bo = (const float*)d_in[15];
    const float* W1 = (const float*)d_in[16]; const float* b1 = (const float*)d_in[17];
    const float* W2 = (const float*)d_in[18]; const float* b2 = (const float*)d_in[19];
    float* out = (float*)d_out;
    const int* src = edge_index;
    const int* dst = edge_index + EE;

    float *qp, *kcp, *vcp, *efw1p, *aggp, *ntp, *nsp, *esp, *zbp;
    __nv_bfloat16 *whi, *wlo, *cefhi, *ceflo, *nfhi, *nflo, *aghi, *aglo, *awhi, *awlo;
    int *nlp;
    cudaGetSymbolAddress((void**)&qp,    g_q);
    cudaGetSymbolAddress((void**)&kcp,   g_kc);
    cudaGetSymbolAddress((void**)&vcp,   g_vc);
    cudaGetSymbolAddress((void**)&efw1p, g_efw1);
    cudaGetSymbolAddress((void**)&aggp,  g_agg);
    cudaGetSymbolAddress((void**)&ntp,   g_nt);
    cudaGetSymbolAddress((void**)&nsp,   g_nscore);
    cudaGetSymbolAddress((void**)&esp,   g_escore);
    cudaGetSymbolAddress((void**)&zbp,   g_zb);
    cudaGetSymbolAddress((void**)&whi,   g_whi);
    cudaGetSymbolAddress((void**)&wlo,   g_wlo);
    cudaGetSymbolAddress((void**)&cefhi, g_cefhi);
    cudaGetSymbolAddress((void**)&ceflo, g_ceflo);
    cudaGetSymbolAddress((void**)&nfhi,  g_nfhi);
    cudaGetSymbolAddress((void**)&nflo,  g_nflo);
    cudaGetSymbolAddress((void**)&aghi,  g_agghi);
    cudaGetSymbolAddress((void**)&aglo,  g_agglo);
    cudaGetSymbolAddress((void**)&awhi,  g_awhi);
    cudaGetSymbolAddress((void**)&awlo,  g_awlo);
    cudaGetSymbolAddress((void**)&nlp,   g_nlive);

    cudaFuncSetAttribute((const void*)mma_gemm<0>, cudaFuncAttributeMaxDynamicSharedMemorySize, GEMM_SMEM);
    cudaFuncSetAttribute((const void*)mma_gemm<4>, cudaFuncAttributeMaxDynamicSharedMemorySize, GEMM_SMEM);

    const size_t SB = (size_t)DE * DE;

    // 0. weight splits (1 kernel) + node-feature split
    wconv_all<<<(DE * DN + 4 * DE * DE + 255) / 256, 256>>>(Wq, Wk, Wv, Wo, W1);
    split_kernel<<<((size_t)NN * DN / 4 + 255) / 256, 256>>>(node_features, nfhi, nflo, (size_t)NN * DN / 4);
    zero_kernel<<<(NN + 255) / 256, 256>>>();

    // 1. exact fp32 scorers
    score_kernel<<<(NN + 7) / 8, 256>>>(node_features, nw, nb, nsp, NN, DN);
    score_kernel<<<(EE + 7) / 8, 256>>>(edge_features, ew, eb, esp, EE, DE);

    // 2. both top-k thresholds (warp-aggregated histogram atomics — the ONE change vs R7)
    topk_kernel<<<2, 1024>>>();

    // 3-5. mask + counts, scans, compaction, CSR
    emask_count_kernel<<<625, 256>>>(src, dst);
    scan2_kernel<<<1, 1024>>>();
    compact_kernel<<<625, 256>>>();
    csr_scatter_kernel<<<(MAXL + 255) / 256, 256>>>(src);

    // 6. gather + split live ef rows
    gather_split_kernel<<<2048, 256>>>(edge_features);

    // 7. GEMMs
    dim3 gq(4, (NN + 127) / 128);
    mma_gemm<0><<<gq, 256, GEMM_SMEM>>>(nfhi, nflo, whi + 0 * SB, wlo + 0 * SB, bq,
                                        qp, nullptr, nullptr, NN, DN, nullptr);
    dim3 gl(4, MAXL / 128);
    mma_gemm<0><<<gl, 256, GEMM_SMEM>>>(cefhi, ceflo, whi + 1 * SB, wlo + 1 * SB, bk,
                                        kcp, nullptr, nullptr, 0, DE, nlp);
    mma_gemm<0><<<gl, 256, GEMM_SMEM>>>(cefhi, ceflo, whi + 2 * SB, wlo + 2 * SB, bv,
                                        vcp, nullptr, nullptr, 0, DE, nlp);
    mma_gemm<0><<<gl, 256, GEMM_SMEM>>>(cefhi, ceflo, whi + 4 * SB, wlo + 4 * SB, zbp,
                                        efw1p, nullptr, nullptr, 0, DE, nlp);

    // 8. attention
    qbk_kernel<<<(NN + 7) / 8, 256>>>(bk);
    attn_live_kernel<<<(MAXL + 7) / 8, 256>>>(src);
    softmax_agg_kernel<<<NN, 256>>>(bv);

    // 9. node-side chain: agg -> aggWo (slot 3, split out) -> nodeterm (slot 4 = W1)
    split_kernel<<<((size_t)NN * DE / 4 + 255) / 256, 256>>>(aggp, aghi, aglo, (size_t)NN * DE / 4);
    mma_gemm<4><<<gq, 256, GEMM_SMEM>>>(aghi, aglo, whi + 3 * SB, wlo + 3 * SB, bo,
                                        nullptr, awhi, awlo, NN, DE, nullptr);
    mma_gemm<0><<<gq, 256, GEMM_SMEM>>>(awhi, awlo, whi + 4 * SB, wlo + 4 * SB, b1,
                                        ntp, nullptr, nullptr, NN, DE, nullptr);

    // 10. outputs
    classify_node_kernel<<<(NN + 7) / 8, 256>>>(W2, b2);
    live_out_kernel<<<(MAXL + 7) / 8, 256>>>(src, W2, b2, out);
    dead_out_kernel<<<(EE + 255) / 256, 256>>>(src, out);
}

// round 12
// speedup vs baseline: 1.2987x; 1.2076x over previous
#include <cuda_runtime.h>
#include <cuda_bf16.h>
#include <math.h>
#include <stdint.h>

// ---------------- problem constants ----------------
#define NN 10000
#define EE 160000
#define DN 256
#define DE 512
#define NH 8
#define NC 10
#define KN 5000
#define KE 80000
#define MAXL 80000   // worst-case live edges

// ---------------- device scratch ----------------
__device__ float g_q[(size_t)NN * DE];
__device__ float g_kc[(size_t)MAXL * DE];
__device__ float g_vc[(size_t)MAXL * DE];
__device__ float g_efw1[(size_t)MAXL * DE];
__device__ float g_scc[(size_t)MAXL * NH];
__device__ float g_qbk[(size_t)NN * NH];
__device__ float g_agg[(size_t)NN * DE];
__device__ float g_nt[(size_t)NN * DE];
__device__ float g_outc[(size_t)NN * NC];
__device__ float g_nscore[NN];
__device__ float g_escore[EE];
__device__ unsigned char g_emask8[EE];
__device__ float g_thr[2];
__device__ float g_zb[DE];
// bf16 hi/lo splits
__device__ __nv_bfloat16 g_cefhi[(size_t)MAXL * DE];
__device__ __nv_bfloat16 g_ceflo[(size_t)MAXL * DE];
__device__ __nv_bfloat16 g_nfhi[(size_t)NN * DN];
__device__ __nv_bfloat16 g_nflo[(size_t)NN * DN];
__device__ __nv_bfloat16 g_agghi[(size_t)NN * DE];
__device__ __nv_bfloat16 g_agglo[(size_t)NN * DE];
__device__ __nv_bfloat16 g_awhi[(size_t)NN * DE];
__device__ __nv_bfloat16 g_awlo[(size_t)NN * DE];
// weights: slot 0=Wq(K=256), 1=Wk, 2=Wv, 3=Wo, 4=W1  ([Nout=512, K] K-major)
__device__ __nv_bfloat16 g_whi[5][DE * DE];
__device__ __nv_bfloat16 g_wlo[5][DE * DE];
// compaction / CSR
__device__ int g_live[MAXL];
__device__ int g_blkcnt[625];
__device__ int g_blkoff[625];
__device__ int g_nlive;
__device__ int g_degt[NN];
__device__ int g_degl[NN];
__device__ int g_off[NN + 1];
__device__ int g_cur[NN];
__device__ int g_elist[MAXL];

// ================= PTX helpers =================
__device__ __forceinline__ void ldm4(uint32_t* r, uint32_t a) {
    asm volatile("ldmatrix.sync.aligned.m8n8.x4.shared.b16 {%0,%1,%2,%3}, [%4];"
                 : "=r"(r[0]), "=r"(r[1]), "=r"(r[2]), "=r"(r[3]) : "r"(a));
}
__device__ __forceinline__ void mma_bf16(float* d, const uint32_t* a, uint32_t b0, uint32_t b1) {
    asm volatile("mma.sync.aligned.m16n8k16.row.col.f32.bf16.bf16.f32 "
                 "{%0,%1,%2,%3},{%4,%5,%6,%7},{%8,%9},{%0,%1,%2,%3};"
                 : "+f"(d[0]), "+f"(d[1]), "+f"(d[2]), "+f"(d[3])
                 : "r"(a[0]), "r"(a[1]), "r"(a[2]), "r"(a[3]), "r"(b0), "r"(b1));
}
__device__ __forceinline__ void cpasync16(uint32_t s, const void* g) {
    asm volatile("cp.async.cg.shared.global [%0], [%1], 16;" :: "r"(s), "l"(g));
}
__device__ __forceinline__ void cp_commit() { asm volatile("cp.async.commit_group;" ::: "memory"); }
#define CP_WAIT(n) asm volatile("cp.async.wait_group %0;" :: "n"(n) : "memory")

__device__ __forceinline__ uint32_t pack2bf(float x, float y) {
    __nv_bfloat162 h = __floats2bfloat162_rn(x, y);
    return *reinterpret_cast<uint32_t*>(&h);
}
__device__ __forceinline__ float gelu_exact(float x) {
    return 0.5f * x * (1.0f + erff(x * 0.70710678118654752f));
}

// ================= scorers: one warp per row =================
__global__ void score_kernel(const float* __restrict__ X, const float* __restrict__ w,
                             const float* __restrict__ b, float* __restrict__ out,
                             int M, int K)
{
    int warp = (blockIdx.x * blockDim.x + threadIdx.x) >> 5;
    int lane = threadIdx.x & 31;
    if (warp >= M) return;
    const float* row = X + (size_t)warp * K;
    float s = 0.f;
    for (int k = lane; k < K; k += 32) s += row[k] * w[k];
    #pragma unroll
    for (int o = 16; o; o >>= 1) s += __shfl_xor_sync(0xFFFFFFFFu, s, o);
    if (lane == 0) out[warp] = s + b[0];
}

// ================= zero init =================
__global__ void zero_kernel() {
    int i = blockIdx.x * blockDim.x + threadIdx.x;
    if (i < NN) { g_degt[i] = 0; g_degl[i] = 0; }
    if (i < DE) g_zb[i] = 0.f;
}

// ================= dual top-k (exact 4x8-bit radix — plain R7 version) =================
__device__ __forceinline__ unsigned f2u_ord(float x) {
    unsigned u = __float_as_uint(x);
    return (u & 0x80000000u) ? ~u : (u | 0x80000000u);
}
__global__ void topk_kernel() {
    int b = blockIdx.x;                       // 0: nodes, 1: edges
    const float* data = b ? g_escore : g_nscore;
    int n = b ? EE : NN;
    unsigned k = b ? KE : KN;
    __shared__ unsigned hist[256];
    __shared__ unsigned prefix_s, krem_s;
    int tid = threadIdx.x;
    if (tid == 0) { prefix_s = 0u; krem_s = k; }
    __syncthreads();
    for (int shift = 24; shift >= 0; shift -= 8) {
        if (tid < 256) hist[tid] = 0u;
        __syncthreads();
        unsigned prefix = prefix_s;
        unsigned maskhi = (shift == 24) ? 0u : (0xFFFFFFFFu << (shift + 8));
        for (int i = tid; i < n; i += blockDim.x) {
            unsigned u = f2u_ord(data[i]);
            if ((u & maskhi) == prefix) atomicAdd(&hist[(u >> shift) & 255], 1u);
        }
        __syncthreads();
        if (tid == 0) {
            unsigned krem = krem_s, cum = 0; int digit = 0;
            for (int d = 255; d >= 0; d--) {
                unsigned c = hist[d];
                if (cum + c >= krem) { digit = d; break; }
                cum += c;
            }
            prefix_s |= ((unsigned)digit) << shift;
            krem_s = krem - cum;
        }
        __syncthreads();
    }
    if (tid == 0) {
        unsigned u = prefix_s;
        u = (u & 0x80000000u) ? (u & 0x7FFFFFFFu) : ~u;
        g_thr[b] = __uint_as_float(u);
    }
}

// ================= edge mask + degree counts + per-block live counts =================
__global__ void emask_count_kernel(const int* __restrict__ src, const int* __restrict__ dst) {
    int e = blockIdx.x * 256 + threadIdx.x;
    bool live = false;
    if (e < EE) {
        float tn = g_thr[0], te = g_thr[1];
        live = (g_escore[e] >= te) && (g_nscore[src[e]] >= tn) && (g_nscore[dst[e]] >= tn);
        g_emask8[e] = live ? 1 : 0;
        atomicAdd(&g_degt[src[e]], 1);
        if (live) atomicAdd(&g_degl[src[e]], 1);
    }
    int cnt = __syncthreads_count(live);
    if (threadIdx.x == 0) g_blkcnt[blockIdx.x] = cnt;
}

// ================= scans =================
__global__ void scan2_kernel() {   // 1 block, 1024 threads
    int t = threadIdx.x;
    if (t == 0) {
        int run = 0;
        for (int i = 0; i < 625; i++) { g_blkoff[i] = run; run += g_blkcnt[i]; }
        g_nlive = run > MAXL ? MAXL : run;
    }
    __syncthreads();
    __shared__ int part[1024];
    const int CH = (NN + 1023) / 1024;
    int s = 0;
    for (int j = 0; j < CH; j++) { int i = t * CH + j; if (i < NN) s += g_degl[i]; }
    part[t] = s;
    __syncthreads();
    if (t == 0) {
        int run = 0;
        for (int i = 0; i < 1024; i++) { int v = part[i]; part[i] = run; run += v; }
        g_off[NN] = run;
    }
    __syncthreads();
    int run = part[t];
    for (int j = 0; j < CH; j++) {
        int i = t * CH + j;
        if (i < NN) { g_off[i] = run; g_cur[i] = run; run += g_degl[i]; }
    }
}

// ================= deterministic order-preserving compaction =================
__global__ void compact_kernel() {
    int e = blockIdx.x * 256 + threadIdx.x;
    bool m = (e < EE) && g_emask8[e];
    int wid = threadIdx.x >> 5, lane = threadIdx.x & 31;
    unsigned bal = __ballot_sync(0xFFFFFFFFu, m);
    __shared__ int wcnt[8];
    if (lane == 0) wcnt[wid] = __popc(bal);
    __syncthreads();
    int woff = 0;
    for (int i = 0; i < wid; i++) woff += wcnt[i];
    if (m) {
        int pos = g_blkoff[blockIdx.x] + woff + __popc(bal & ((1u << lane) - 1));
        if (pos < MAXL) g_live[pos] = e;
    }
}

// ================= CSR scatter of compact indices by src node =================
__global__ void csr_scatter_kernel(const int* __restrict__ src) {
    int c = blockIdx.x * 256 + threadIdx.x;
    if (c < g_nlive) {
        int e = g_live[c];
        int p = atomicAdd(&g_cur[src[e]], 1);
        g_elist[p] = c;
    }
}

// ================= gather + split live ef rows =================
__global__ void gather_split_kernel(const float* __restrict__ ef) {
    int nl = g_nlive;
    size_t total = (size_t)nl * 128;
    size_t stride = (size_t)gridDim.x * blockDim.x;
    for (size_t id = (size_t)blockIdx.x * blockDim.x + threadIdx.x; id < total; id += stride) {
        int c = (int)(id >> 7), j = (int)(id & 127);
        int e = g_live[c];
        float4 x = reinterpret_cast<const float4*>(ef)[(size_t)e * 128 + j];
        __nv_bfloat162 h0 = __floats2bfloat162_rn(x.x, x.y);
        __nv_bfloat162 h1 = __floats2bfloat162_rn(x.z, x.w);
        uint2 hv, lv;
        hv.x = *reinterpret_cast<uint32_t*>(&h0);
        hv.y = *reinterpret_cast<uint32_t*>(&h1);
        lv.x = pack2bf(x.x - __bfloat162float(h0.x), x.y - __bfloat162float(h0.y));
        lv.y = pack2bf(x.z - __bfloat162float(h1.x), x.w - __bfloat162float(h1.y));
        reinterpret_cast<uint2*>(g_cefhi)[(size_t)c * 128 + j] = hv;
        reinterpret_cast<uint2*>(g_ceflo)[(size_t)c * 128 + j] = lv;
    }
}

// ================= generic fp32 -> bf16 hi/lo split =================
__global__ void split_kernel(const float* __restrict__ X, __nv_bfloat16* __restrict__ hi,
                             __nv_bfloat16* __restrict__ lo, size_t n4)
{
    size_t i = (size_t)blockIdx.x * blockDim.x + threadIdx.x;
    if (i >= n4) return;
    float4 x = reinterpret_cast<const float4*>(X)[i];
    __nv_bfloat162 h0 = __floats2bfloat162_rn(x.x, x.y);
    __nv_bfloat162 h1 = __floats2bfloat162_rn(x.z, x.w);
    uint2 hv, lv;
    hv.x = *reinterpret_cast<uint32_t*>(&h0);
    hv.y = *reinterpret_cast<uint32_t*>(&h1);
    lv.x = pack2bf(x.x - __bfloat162float(h0.x), x.y - __bfloat162float(h0.y));
    lv.y = pack2bf(x.z - __bfloat162float(h1.x), x.w - __bfloat162float(h1.y));
    reinterpret_cast<uint2*>(hi)[i] = hv;
    reinterpret_cast<uint2*>(lo)[i] = lv;
}

// ================= all 5 weight transposes + splits =================
// slots: 0=Wq(K=256), 1=Wk, 2=Wv, 3=Wo, 4=W1
__global__ void wconv_all(const float* __restrict__ Wq, const float* __restrict__ Wk,
                          const float* __restrict__ Wv, const float* __restrict__ Wo,
                          const float* __restrict__ W1)
{
    int idx = blockIdx.x * 256 + threadIdx.x;
    const int S0 = DE * DN;
    const int SB = DE * DE;
    int slot, K, r;
    const float* W;
    if (idx < S0) { slot = 0; K = DN; r = idx; W = Wq; }
    else {
        int t = idx - S0;
        slot = 1 + t / SB;
        if (slot > 4) return;
        r = t % SB; K = DE;
        W = (slot == 1) ? Wk : (slot == 2) ? Wv : (slot == 3) ? Wo : W1;
    }
    int n = r % DE, k = r / DE;
    float x = W[(size_t)k * DE + n];
    __nv_bfloat16 h = __float2bfloat16(x);
    g_whi[slot][n * K + k] = h;
    g_wlo[slot][n * K + k] = __float2bfloat16(x - __bfloat162float(h));
}

// ================= mma.sync bf16-split GEMM (pre-split A & B) =================
// C[M,512] = A[M,K] @ W^T + bias ; EPI 0: fp32 C ; EPI 4: split bf16 Chi/Clo
#define STAGE_BYTES 65536
#define GEMM_SMEM (3 * STAGE_BYTES)

template<int EPI>
__global__ __launch_bounds__(256, 1)
void mma_gemm(const __nv_bfloat16* __restrict__ Ahi, const __nv_bfloat16* __restrict__ Alo,
              const __nv_bfloat16* __restrict__ Bhi, const __nv_bfloat16* __restrict__ Blo,
              const float* __restrict__ bias, float* __restrict__ C,
              __nv_bfloat16* __restrict__ Chi, __nv_bfloat16* __restrict__ Clo,
              int Mstat, int K, const int* __restrict__ Mdyn)
{
    const int M = Mdyn ? *Mdyn : Mstat;
    const int row0 = blockIdx.y * 128;
    if (row0 >= M) return;
    extern __shared__ char sm[];
    const uint32_t sbase = (uint32_t)__cvta_generic_to_shared(sm);
    const int tid = threadIdx.x;
    const int w = tid >> 5, l = tid & 31;
    const int n0 = blockIdx.x * 128;
    const int wm = w >> 2, wn = w & 3;

    float acc[4][4][4];
    #pragma unroll
    for (int i = 0; i < 4; i++)
        #pragma unroll
        for (int j = 0; j < 4; j++)
            #pragma unroll
            for (int p = 0; p < 4; p++) acc[i][j][p] = 0.f;

    int srow[4];
    #pragma unroll
    for (int i = 0; i < 4; i++) {
        int r = row0 + (tid >> 3) + 32 * i;
        srow[i] = (r >= M) ? (M - 1) : r;
    }

    auto loadA = [&](int k0, int stage) {
        uint32_t sb = sbase + stage * STAGE_BYTES;
        #pragma unroll
        for (int i = 0; i < 4; i++) {
            int lin = tid + 256 * i;
            int r = lin >> 3, ch = lin & 7;
            uint32_t so = sb + r * 128 + (uint32_t)((ch ^ (r & 7)) * 16);
            size_t gi = (size_t)srow[i] * K + k0 + ch * 8;
            cpasync16(so, &Ahi[gi]);
            cpasync16(so + 16384, &Alo[gi]);
        }
    };
    auto loadB = [&](int k0, int stage) {
        uint32_t sb = sbase + stage * STAGE_BYTES + 32768;
        #pragma unroll
        for (int i = 0; i < 4; i++) {
            int lin = tid + 256 * i;
            int r = lin >> 3, ch = lin & 7;
            uint32_t so = sb + r * 128 + (uint32_t)((ch ^ (r & 7)) * 16);
            size_t gi = (size_t)(n0 + r) * K + k0 + ch * 8;
            cpasync16(so, &Bhi[gi]);
            cpasync16(so + 16384, &Blo[gi]);
        }
    };
    auto compute = [&](int stage) {
        uint32_t ab = sbase + stage * STAGE_BYTES;
        uint32_t bb = ab + 32768;
        #pragma unroll
        for (int ks = 0; ks < 4; ks++) {
            int kc = ks * 2;
            uint32_t ahi[4][4], alo[4][4];
            #pragma unroll
            for (int mf = 0; mf < 4; mf++) {
                int rr = wm * 64 + mf * 16 + (l & 15);
                int kch = kc + (l >> 4);
                uint32_t addr = ab + rr * 128 + (uint32_t)(((kch ^ (rr & 7))) * 16);
                ldm4(ahi[mf], addr);
                ldm4(alo[mf], addr + 16384);
            }
            uint32_t bhi[2][4], blo[2][4];
            #pragma unroll
            for (int ng = 0; ng < 2; ng++) {
                int nr = wn * 32 + ng * 16 + (l & 7) + ((l >> 4) << 3);
                int kch = kc + ((l >> 3) & 1);
                uint32_t addr = bb + nr * 128 + (uint32_t)(((kch ^ (nr & 7))) * 16);
                ldm4(bhi[ng], addr);
                ldm4(blo[ng], addr + 16384);
            }
            #pragma unroll
            for (int mf = 0; mf < 4; mf++) {
                #pragma unroll
                for (int nf = 0; nf < 4; nf++) {
                    int ng = nf >> 1, sb2 = (nf & 1) * 2;
                    mma_bf16(acc[mf][nf], ahi[mf], bhi[ng][sb2], bhi[ng][sb2 + 1]);
                    mma_bf16(acc[mf][nf], ahi[mf], blo[ng][sb2], blo[ng][sb2 + 1]);
                    mma_bf16(acc[mf][nf], alo[mf], bhi[ng][sb2], bhi[ng][sb2 + 1]);
                }
            }
        }
    };

    const int nch = K >> 6;
    loadA(0, 0); loadB(0, 0); cp_commit();
    if (nch > 1) { loadA(64, 1); loadB(64, 1); cp_commit(); }
    else cp_commit();
    for (int c = 0; c < nch; c++) {
        __syncthreads();
        if (c + 2 < nch) { loadA((c + 2) * 64, (c + 2) % 3); loadB((c + 2) * 64, (c + 2) % 3); }
        cp_commit();
        CP_WAIT(2);
        __syncthreads();
        compute(c % 3);
    }

    #pragma unroll
    for (int mf = 0; mf < 4; mf++) {
        int gr0 = row0 + wm * 64 + mf * 16 + (l >> 2);
        #pragma unroll
        for (int nf = 0; nf < 4; nf++) {
            int gc = n0 + wn * 32 + nf * 8 + (l & 3) * 2;
            float b0 = bias[gc], b1 = bias[gc + 1];
            #pragma unroll
            for (int h = 0; h < 2; h++) {
                int grow = gr0 + 8 * h;
                if (grow >= M) continue;
                float v0 = acc[mf][nf][2 * h] + b0;
                float v1 = acc[mf][nf][2 * h + 1] + b1;
                if (EPI == 4) {
                    __nv_bfloat162 hh = __floats2bfloat162_rn(v0, v1);
                    uint32_t hw = *reinterpret_cast<uint32_t*>(&hh);
                    uint32_t lw = pack2bf(v0 - __bfloat162float(hh.x), v1 - __bfloat162float(hh.y));
                    *reinterpret_cast<uint32_t*>(&Chi[(size_t)grow * DE + gc]) = hw;
                    *reinterpret_cast<uint32_t*>(&Clo[(size_t)grow * DE + gc]) = lw;
                } else {
                    *reinterpret_cast<float2*>(&C[(size_t)grow * DE + gc]) = make_float2(v0, v1);
                }
            }
        }
    }
}

// ================= qbk: dead-edge logit per node/head =================
__global__ void qbk_kernel(const float* __restrict__ bk) {
    int n = blockIdx.x * 8 + (threadIdx.x >> 5);
    int lane = threadIdx.x & 31;
    if (n >= NN) return;
    const float4* qr = reinterpret_cast<const float4*>(g_q + (size_t)n * DE);
    const float4* br = reinterpret_cast<const float4*>(bk);
    float s = 0.f;
    int base = lane * 4;
    #pragma unroll
    for (int j = 0; j < 4; j++) {
        float4 a = qr[base + j], b = br[base + j];
        s += a.x * b.x + a.y * b.y + a.z * b.z + a.w * b.w;
    }
    s += __shfl_xor_sync(0xFFFFFFFFu, s, 1);
    s += __shfl_xor_sync(0xFFFFFFFFu, s, 2);
    if ((lane & 3) == 0) g_qbk[(size_t)n * NH + (lane >> 2)] = s * 0.125f;
}

// ================= attention logits: one warp per live edge =================
__global__ void attn_live_kernel(const int* __restrict__ src) {
    int c = blockIdx.x * 8 + (threadIdx.x >> 5);
    int lane = threadIdx.x & 31;
    if (c >= g_nlive) return;
    int e = g_live[c];
    const float4* qr = reinterpret_cast<const float4*>(g_q + (size_t)src[e] * DE);
    const float4* kr = reinterpret_cast<const float4*>(g_kc + (size_t)c * DE);
    float s = 0.f;
    int base = lane * 4;
    #pragma unroll
    for (int j = 0; j < 4; j++) {
        float4 a = qr[base + j], b = kr[base + j];
        s += a.x * b.x + a.y * b.y + a.z * b.z + a.w * b.w;
    }
    s += __shfl_xor_sync(0xFFFFFFFFu, s, 1);
    s += __shfl_xor_sync(0xFFFFFFFFu, s, 2);
    if ((lane & 3) == 0) g_scc[(size_t)c * NH + (lane >> 2)] = s * 0.125f;
}

// ================= segment softmax + aggregation (live + analytic dead) =================
__global__ void softmax_agg_kernel(const float* __restrict__ bv) {
    int n = blockIdx.x;
    int off = g_off[n];
    int degl = g_off[n + 1] - off;
    int ndead = g_degt[n] - degl;
    int tid = threadIdx.x;
    int wid = tid >> 5, lane = tid & 31;
    int d0 = tid * 2;

    if (degl + ndead == 0) {
        *reinterpret_cast<float2*>(g_agg + (size_t)n * DE + d0) = make_float2(0.f, 0.f);
        return;
    }
    __shared__ float m_sh[NH], d_sh[NH], cdead_sh[NH];
    __shared__ float attn_sh[64 * NH];
    {
        float qb = g_qbk[(size_t)n * NH + wid];
        float mx = -INFINITY;
        for (int i = lane; i < degl; i += 32) {
            int c = g_elist[off + i];
            mx = fmaxf(mx, g_scc[(size_t)c * NH + wid]);
        }
        #pragma unroll
        for (int o = 16; o; o >>= 1) mx = fmaxf(mx, __shfl_xor_sync(0xFFFFFFFFu, mx, o));
        if (ndead > 0) mx = fmaxf(mx, qb);
        float sm = 0.f;
        for (int i = lane; i < degl; i += 32) {
            int c = g_elist[off + i];
            sm += expf(g_scc[(size_t)c * NH + wid] - mx);
        }
        #pragma unroll
        for (int o = 16; o; o >>= 1) sm += __shfl_xor_sync(0xFFFFFFFFu, sm, o);
        if (lane == 0) {
            float dterm = (ndead > 0) ? (float)ndead * expf(qb - mx) : 0.f;
            float den = sm + dterm;
            m_sh[wid] = mx; d_sh[wid] = den; cdead_sh[wid] = dterm / den;
        }
    }
    __syncthreads();
    float2 acc = make_float2(0.f, 0.f);
    int h = d0 >> 6;
    for (int base = 0; base < degl; base += 64) {
        int cnt = min(64, degl - base);
        __syncthreads();
        for (int idx = tid; idx < cnt * NH; idx += 256) {
            int j = idx >> 3, hh = idx & 7;
            int c = g_elist[off + base + j];
            attn_sh[idx] = expf(g_scc[(size_t)c * NH + hh] - m_sh[hh]) / d_sh[hh];
        }
        __syncthreads();
        for (int j = 0; j < cnt; j++) {
            int c = g_elist[off + base + j];
            float a = attn_sh[j * NH + h];
            float2 vv = *reinterpret_cast<const float2*>(g_vc + (size_t)c * DE + d0);
            acc.x += a * vv.x;
            acc.y += a * vv.y;
        }
    }
    float cd = cdead_sh[h];
    acc.x += cd * bv[d0];
    acc.y += cd * bv[d0 + 1];
    *reinterpret_cast<float2*>(g_agg + (size_t)n * DE + d0) = acc;
}

// ================= per-node classifier (dead-edge output) =================
__global__ void classify_node_kernel(const float* __restrict__ W2, const float* __restrict__ b2) {
    __shared__ float W2s[DE * NC];
    int tid = threadIdx.x;
    for (int i = tid; i < DE * NC; i += 256) W2s[i] = W2[i];
    __syncthreads();
    int n = blockIdx.x * 8 + (tid >> 5);
    if (n >= NN) return;
    int lane = tid & 31;
    const float* ntr = g_nt + (size_t)n * DE;
    float p[NC];
    #pragma unroll
    for (int c = 0; c < NC; c++) p[c] = 0.f;
    for (int k = lane; k < DE; k += 32) {
        float hv = gelu_exact(ntr[k]);
        const float* wk = &W2s[k * NC];
        #pragma unroll
        for (int c = 0; c < NC; c++) p[c] += hv * wk[c];
    }
    #pragma unroll
    for (int c = 0; c < NC; c++) {
        #pragma unroll
        for (int o = 16; o; o >>= 1) p[c] += __shfl_xor_sync(0xFFFFFFFFu, p[c], o);
    }
    if (lane == 0) {
        #pragma unroll
        for (int c = 0; c < NC; c++) g_outc[(size_t)n * NC + c] = p[c] + b2[c];
    }
}

// ================= live-edge output: gelu(nt[src]+efW1) @ W2 =================
__global__ void live_out_kernel(const int* __restrict__ src, const float* __restrict__ W2,
                                const float* __restrict__ b2, float* __restrict__ out) {
    __shared__ float W2s[DE * NC];
    int tid = threadIdx.x;
    for (int i = tid; i < DE * NC; i += 256) W2s[i] = W2[i];
    __syncthreads();
    int c = blockIdx.x * 8 + (tid >> 5);
    if (c >= g_nlive) return;
    int e = g_live[c];
    int lane = tid & 31;
    const float* ntr = g_nt + (size_t)src[e] * DE;
    const float* fr = g_efw1 + (size_t)c * DE;
    float p[NC];
    #pragma unroll
    for (int cc = 0; cc < NC; cc++) p[cc] = 0.f;
    for (int k = lane; k < DE; k += 32) {
        float hv = gelu_exact(ntr[k] + fr[k]);
        const float* wk = &W2s[k * NC];
        #pragma unroll
        for (int cc = 0; cc < NC; cc++) p[cc] += hv * wk[cc];
    }
    #pragma unroll
    for (int cc = 0; cc < NC; cc++) {
        #pragma unroll
        for (int o = 16; o; o >>= 1) p[cc] += __shfl_xor_sync(0xFFFFFFFFu, p[cc], o);
    }
    if (lane == 0) {
        #pragma unroll
        for (int cc = 0; cc < NC; cc++) out[(size_t)e * NC + cc] = p[cc] + b2[cc];
    }
}

// ================= dead-edge output: copy per-node classifier =================
__global__ void dead_out_kernel(const int* __restrict__ src, float* __restrict__ out) {
    int e = blockIdx.x * 256 + threadIdx.x;
    if (e >= EE || g_emask8[e]) return;
    const float* s = g_outc + (size_t)src[e] * NC;
    float* d = out + (size_t)e * NC;
    #pragma unroll
    for (int c = 0; c < NC; c++) d[c] = s[c];
}

// ================= host launcher (stream-fork DAG) =================
extern "C" void kernel_launch(void* const* d_in, const int* in_sizes, int n_in,
                              void* d_out, int out_size)
{
    const float* node_features = (const float*)d_in[0];
    const float* edge_features = (const float*)d_in[1];
    const int*   edge_index    = (const int*)d_in[2];
    const float* nw = (const float*)d_in[4];
    const float* nb = (const float*)d_in[5];
    const float* ew = (const float*)d_in[6];
    const float* eb = (const float*)d_in[7];
    const float* Wq = (const float*)d_in[8];  const float* bq = (const float*)d_in[9];
    const float* Wk = (const float*)d_in[10]; const float* bk = (const float*)d_in[11];
    const float* Wv = (const float*)d_in[12]; const float* bv = (const float*)d_in[13];
    const float* Wo = (const float*)d_in[14]; const float* bo = (const float*)d_in[15];
    const float* W1 = (const float*)d_in[16]; const float* b1 = (const float*)d_in[17];
    const float* W2 = (const float*)d_in[18]; const float* b2 = (const float*)d_in[19];
    float* out = (float*)d_out;
    const int* src = edge_index;
    const int* dst = edge_index + EE;

    float *qp, *kcp, *vcp, *efw1p, *aggp, *ntp, *nsp, *esp, *zbp;
    __nv_bfloat16 *whi, *wlo, *cefhi, *ceflo, *nfhi, *nflo, *aghi, *aglo, *awhi, *awlo;
    int *nlp;
    cudaGetSymbolAddress((void**)&qp,    g_q);
    cudaGetSymbolAddress((void**)&kcp,   g_kc);
    cudaGetSymbolAddress((void**)&vcp,   g_vc);
    cudaGetSymbolAddress((void**)&efw1p, g_efw1);
    cudaGetSymbolAddress((void**)&aggp,  g_agg);
    cudaGetSymbolAddress((void**)&ntp,   g_nt);
    cudaGetSymbolAddress((void**)&nsp,   g_nscore);
    cudaGetSymbolAddress((void**)&esp,   g_escore);
    cudaGetSymbolAddress((void**)&zbp,   g_zb);
    cudaGetSymbolAddress((void**)&whi,   g_whi);
    cudaGetSymbolAddress((void**)&wlo,   g_wlo);
    cudaGetSymbolAddress((void**)&cefhi, g_cefhi);
    cudaGetSymbolAddress((void**)&ceflo, g_ceflo);
    cudaGetSymbolAddress((void**)&nfhi,  g_nfhi);
    cudaGetSymbolAddress((void**)&nflo,  g_nflo);
    cudaGetSymbolAddress((void**)&aghi,  g_agghi);
    cudaGetSymbolAddress((void**)&aglo,  g_agglo);
    cudaGetSymbolAddress((void**)&awhi,  g_awhi);
    cudaGetSymbolAddress((void**)&awlo,  g_awlo);
    cudaGetSymbolAddress((void**)&nlp,   g_nlive);

    cudaFuncSetAttribute((const void*)mma_gemm<0>, cudaFuncAttributeMaxDynamicSharedMemorySize, GEMM_SMEM);
    cudaFuncSetAttribute((const void*)mma_gemm<4>, cudaFuncAttributeMaxDynamicSharedMemorySize, GEMM_SMEM);

    const size_t SB = (size_t)DE * DE;

    // ---- stream / event setup (capture-safe fork from legacy stream) ----
    cudaStream_t sA = 0;   // legacy stream = capture origin
    cudaStream_t sB, sC;
    cudaStreamCreateWithFlags(&sB, cudaStreamNonBlocking);
    cudaStreamCreateWithFlags(&sC, cudaStreamNonBlocking);
    enum { EV_ROOT, EV_WCONV, EV_NSC, EV_QBK, EV_CMP, EV_GATHER, EV_CSR, EV_EFW1, EV_CLS, EV_DEAD, NEV };
    cudaEvent_t ev[NEV];
    for (int i = 0; i < NEV; i++) cudaEventCreateWithFlags(&ev[i], cudaEventDisableTiming);

    // fork: B and C branch off the legacy stream
    cudaEventRecord(ev[EV_ROOT], sA);
    cudaStreamWaitEvent(sB, ev[EV_ROOT], 0);
    cudaStreamWaitEvent(sC, ev[EV_ROOT], 0);

    // ---- stream B: weight splits -> (wait compact) csr -> (wait gather) efw1 GEMM -> (wait classify) dead_out
    wconv_all<<<(DE * DN + 4 * DE * DE + 255) / 256, 256, 0, sB>>>(Wq, Wk, Wv, Wo, W1);
    cudaEventRecord(ev[EV_WCONV], sB);

    // ---- stream C: nf split -> node scorer -> (wait wconv) q GEMM -> qbk
    split_kernel<<<((size_t)NN * DN / 4 + 255) / 256, 256, 0, sC>>>(node_features, nfhi, nflo, (size_t)NN * DN / 4);
    score_kernel<<<(NN + 7) / 8, 256, 0, sC>>>(node_features, nw, nb, nsp, NN, DN);
    cudaEventRecord(ev[EV_NSC], sC);
    cudaStreamWaitEvent(sC, ev[EV_WCONV], 0);
    dim3 gq(4, (NN + 127) / 128);
    mma_gemm<0><<<gq, 256, GEMM_SMEM, sC>>>(nfhi, nflo, whi + 0 * SB, wlo + 0 * SB, bq,
                                            qp, nullptr, nullptr, NN, DN, nullptr);
    qbk_kernel<<<(NN + 7) / 8, 256, 0, sC>>>(bk);
    cudaEventRecord(ev[EV_QBK], sC);

    // ---- stream A (legacy): zero, edge scorer, topk, mask, scans, compact, gather, k/v GEMMs, attention chain
    zero_kernel<<<(NN + 255) / 256, 256, 0, sA>>>();
    score_kernel<<<(EE + 7) / 8, 256, 0, sA>>>(edge_features, ew, eb, esp, EE, DE);
    cudaStreamWaitEvent(sA, ev[EV_NSC], 0);
    topk_kernel<<<2, 1024, 0, sA>>>();
    emask_count_kernel<<<625, 256, 0, sA>>>(src, dst);
    scan2_kernel<<<1, 1024, 0, sA>>>();
    compact_kernel<<<625, 256, 0, sA>>>();
    cudaEventRecord(ev[EV_CMP], sA);
    gather_split_kernel<<<2048, 256, 0, sA>>>(edge_features);
    cudaEventRecord(ev[EV_GATHER], sA);

    // B: csr_scatter (needs compact + scan2)
    cudaStreamWaitEvent(sB, ev[EV_CMP], 0);
    csr_scatter_kernel<<<(MAXL + 255) / 256, 256, 0, sB>>>(src);
    cudaEventRecord(ev[EV_CSR], sB);
    // B: efw1 GEMM (needs gather + wconv[same stream])
    cudaStreamWaitEvent(sB, ev[EV_GATHER], 0);
    dim3 gl(4, MAXL / 128);
    mma_gemm<0><<<gl, 256, GEMM_SMEM, sB>>>(cefhi, ceflo, whi + 4 * SB, wlo + 4 * SB, zbp,
                                            efw1p, nullptr, nullptr, 0, DE, nlp);
    cudaEventRecord(ev[EV_EFW1], sB);

    // A: k/v GEMMs (need wconv)
    cudaStreamWaitEvent(sA, ev[EV_WCONV], 0);
    mma_gemm<0><<<gl, 256, GEMM_SMEM, sA>>>(cefhi, ceflo, whi + 1 * SB, wlo + 1 * SB, bk,
                                            kcp, nullptr, nullptr, 0, DE, nlp);
    mma_gemm<0><<<gl, 256, GEMM_SMEM, sA>>>(cefhi, ceflo, whi + 2 * SB, wlo + 2 * SB, bv,
                                            vcp, nullptr, nullptr, 0, DE, nlp);

    // A: attention (needs q from C, csr from B)
    cudaStreamWaitEvent(sA, ev[EV_QBK], 0);
    attn_live_kernel<<<(MAXL + 7) / 8, 256, 0, sA>>>(src);
    cudaStreamWaitEvent(sA, ev[EV_CSR], 0);
    softmax_agg_kernel<<<NN, 256, 0, sA>>>(bv);

    // A: node-side chain
    split_kernel<<<((size_t)NN * DE / 4 + 255) / 256, 256, 0, sA>>>(aggp, aghi, aglo, (size_t)NN * DE / 4);
    mma_gemm<4><<<gq, 256, GEMM_SMEM, sA>>>(aghi, aglo, whi + 3 * SB, wlo + 3 * SB, bo,
                                            nullptr, awhi, awlo, NN, DE, nullptr);
    mma_gemm<0><<<gq, 256, GEMM_SMEM, sA>>>(awhi, awlo, whi + 4 * SB, wlo + 4 * SB, b1,
                                            ntp, nullptr, nullptr, NN, DE, nullptr);
    classify_node_kernel<<<(NN + 7) / 8, 256, 0, sA>>>(W2, b2);
    cudaEventRecord(ev[EV_CLS], sA);

    // B: dead-edge output (needs classify + emask)
    cudaStreamWaitEvent(sB, ev[EV_CLS], 0);
    dead_out_kernel<<<(EE + 255) / 256, 256, 0, sB>>>(src, out);
    cudaEventRecord(ev[EV_DEAD], sB);

    // A: live-edge output (needs nt + efw1)
    cudaStreamWaitEvent(sA, ev[EV_EFW1], 0);
    live_out_kernel<<<(MAXL + 7) / 8, 256, 0, sA>>>(src, W2, b2, out);

    // join everything back into the legacy stream
    cudaStreamWaitEvent(sA, ev[EV_DEAD], 0);

    // cleanup: only destroy when NOT capturing (destroying a captured stream invalidates capture)
    cudaStreamCaptureStatus cap = cudaStreamCaptureStatusNone;
    cudaStreamIsCapturing(sA, &cap);
    if (cap == cudaStreamCaptureStatusNone) {
        cudaStreamDestroy(sB);
        cudaStreamDestroy(sC);
        for (int i = 0; i < NEV; i++) cudaEventDestroy(ev[i]);
    }
}

// round 13
// speedup vs baseline: 1.3294x; 1.0236x over previous
#include <cuda_runtime.h>
#include <cuda_bf16.h>
#include <math.h>
#include <stdint.h>

// ---------------- problem constants ----------------
#define NN 10000
#define EE 160000
#define DN 256
#define DE 512
#define NH 8
#define NC 10
#define KN 5000
#define KE 80000
#define MAXL 80000   // worst-case live edges

// ---------------- device scratch ----------------
__device__ float g_q[(size_t)NN * DE];
__device__ float g_kc[(size_t)MAXL * DE];
__device__ float g_vc[(size_t)MAXL * DE];
__device__ float g_efw1[(size_t)MAXL * DE];
__device__ float g_scc[(size_t)MAXL * NH];
__device__ float g_qbk[(size_t)NN * NH];
__device__ float g_agg[(size_t)NN * DE];
__device__ float g_nt[(size_t)NN * DE];
__device__ float g_outc[(size_t)NN * NC];
__device__ float g_nscore[NN];
__device__ float g_escore[EE];
__device__ unsigned char g_emask8[EE];
__device__ float g_thr[2];
__device__ float g_zb[DE];
// bf16 hi/lo splits
__device__ __nv_bfloat16 g_cefhi[(size_t)MAXL * DE];
__device__ __nv_bfloat16 g_ceflo[(size_t)MAXL * DE];
__device__ __nv_bfloat16 g_nfhi[(size_t)NN * DN];
__device__ __nv_bfloat16 g_nflo[(size_t)NN * DN];
__device__ __nv_bfloat16 g_agghi[(size_t)NN * DE];
__device__ __nv_bfloat16 g_agglo[(size_t)NN * DE];
__device__ __nv_bfloat16 g_awhi[(size_t)NN * DE];
__device__ __nv_bfloat16 g_awlo[(size_t)NN * DE];
// weights: slot 0=Wq(K=256), 1=Wk, 2=Wv, 3=Wo, 4=W1  ([Nout=512, K] K-major)
__device__ __nv_bfloat16 g_whi[5][DE * DE];
__device__ __nv_bfloat16 g_wlo[5][DE * DE];
// compaction / CSR
__device__ int g_live[MAXL];
__device__ int g_blkcnt[625];
__device__ int g_blkoff[625];
__device__ int g_nlive;
__device__ int g_degt[NN];
__device__ int g_degl[NN];
__device__ int g_off[NN + 1];
__device__ int g_cur[NN];
__device__ int g_elist[MAXL];

// ================= PTX helpers =================
__device__ __forceinline__ void ldm4(uint32_t* r, uint32_t a) {
    asm volatile("ldmatrix.sync.aligned.m8n8.x4.shared.b16 {%0,%1,%2,%3}, [%4];"
                 : "=r"(r[0]), "=r"(r[1]), "=r"(r[2]), "=r"(r[3]) : "r"(a));
}
__device__ __forceinline__ void mma_bf16(float* d, const uint32_t* a, uint32_t b0, uint32_t b1) {
    asm volatile("mma.sync.aligned.m16n8k16.row.col.f32.bf16.bf16.f32 "
                 "{%0,%1,%2,%3},{%4,%5,%6,%7},{%8,%9},{%0,%1,%2,%3};"
                 : "+f"(d[0]), "+f"(d[1]), "+f"(d[2]), "+f"(d[3])
                 : "r"(a[0]), "r"(a[1]), "r"(a[2]), "r"(a[3]), "r"(b0), "r"(b1));
}
__device__ __forceinline__ void cpasync16(uint32_t s, const void* g) {
    asm volatile("cp.async.cg.shared.global [%0], [%1], 16;" :: "r"(s), "l"(g));
}
__device__ __forceinline__ void cp_commit() { asm volatile("cp.async.commit_group;" ::: "memory"); }
#define CP_WAIT(n) asm volatile("cp.async.wait_group %0;" :: "n"(n) : "memory")

__device__ __forceinline__ uint32_t pack2bf(float x, float y) {
    __nv_bfloat162 h = __floats2bfloat162_rn(x, y);
    return *reinterpret_cast<uint32_t*>(&h);
}
__device__ __forceinline__ float gelu_exact(float x) {
    return 0.5f * x * (1.0f + erff(x * 0.70710678118654752f));
}

// ================= scorers: one warp per row =================
__global__ void score_kernel(const float* __restrict__ X, const float* __restrict__ w,
                             const float* __restrict__ b, float* __restrict__ out,
                             int M, int K)
{
    int warp = (blockIdx.x * blockDim.x + threadIdx.x) >> 5;
    int lane = threadIdx.x & 31;
    if (warp >= M) return;
    const float* row = X + (size_t)warp * K;
    float s = 0.f;
    for (int k = lane; k < K; k += 32) s += row[k] * w[k];
    #pragma unroll
    for (int o = 16; o; o >>= 1) s += __shfl_xor_sync(0xFFFFFFFFu, s, o);
    if (lane == 0) out[warp] = s + b[0];
}

// ================= zero init =================
__global__ void zero_kernel() {
    int i = blockIdx.x * blockDim.x + threadIdx.x;
    if (i < NN) { g_degt[i] = 0; g_degl[i] = 0; }
    if (i < DE) g_zb[i] = 0.f;
}

// ================= dual top-k (exact 4x8-bit radix) =================
__device__ __forceinline__ unsigned f2u_ord(float x) {
    unsigned u = __float_as_uint(x);
    return (u & 0x80000000u) ? ~u : (u | 0x80000000u);
}
__global__ void topk_kernel() {
    int b = blockIdx.x;                       // 0: nodes, 1: edges
    const float* data = b ? g_escore : g_nscore;
    int n = b ? EE : NN;
    unsigned k = b ? KE : KN;
    __shared__ unsigned hist[256];
    __shared__ unsigned prefix_s, krem_s;
    int tid = threadIdx.x;
    if (tid == 0) { prefix_s = 0u; krem_s = k; }
    __syncthreads();
    for (int shift = 24; shift >= 0; shift -= 8) {
        if (tid < 256) hist[tid] = 0u;
        __syncthreads();
        unsigned prefix = prefix_s;
        unsigned maskhi = (shift == 24) ? 0u : (0xFFFFFFFFu << (shift + 8));
        for (int i = tid; i < n; i += blockDim.x) {
            unsigned u = f2u_ord(data[i]);
            if ((u & maskhi) == prefix) atomicAdd(&hist[(u >> shift) & 255], 1u);
        }
        __syncthreads();
        if (tid == 0) {
            unsigned krem = krem_s, cum = 0; int digit = 0;
            for (int d = 255; d >= 0; d--) {
                unsigned c = hist[d];
                if (cum + c >= krem) { digit = d; break; }
                cum += c;
            }
            prefix_s |= ((unsigned)digit) << shift;
            krem_s = krem - cum;
        }
        __syncthreads();
    }
    if (tid == 0) {
        unsigned u = prefix_s;
        u = (u & 0x80000000u) ? (u & 0x7FFFFFFFu) : ~u;
        g_thr[b] = __uint_as_float(u);
    }
}

// ================= edge mask + degree counts + per-block live counts =================
__global__ void emask_count_kernel(const int* __restrict__ src, const int* __restrict__ dst) {
    int e = blockIdx.x * 256 + threadIdx.x;
    bool live = false;
    if (e < EE) {
        float tn = g_thr[0], te = g_thr[1];
        live = (g_escore[e] >= te) && (g_nscore[src[e]] >= tn) && (g_nscore[dst[e]] >= tn);
        g_emask8[e] = live ? 1 : 0;
        atomicAdd(&g_degt[src[e]], 1);
        if (live) atomicAdd(&g_degl[src[e]], 1);
    }
    int cnt = __syncthreads_count(live);
    if (threadIdx.x == 0) g_blkcnt[blockIdx.x] = cnt;
}

// ================= scans =================
__global__ void scan2_kernel() {   // 1 block, 1024 threads
    int t = threadIdx.x;
    if (t == 0) {
        int run = 0;
        for (int i = 0; i < 625; i++) { g_blkoff[i] = run; run += g_blkcnt[i]; }
        g_nlive = run > MAXL ? MAXL : run;
    }
    __syncthreads();
    __shared__ int part[1024];
    const int CH = (NN + 1023) / 1024;
    int s = 0;
    for (int j = 0; j < CH; j++) { int i = t * CH + j; if (i < NN) s += g_degl[i]; }
    part[t] = s;
    __syncthreads();
    if (t == 0) {
        int run = 0;
        for (int i = 0; i < 1024; i++) { int v = part[i]; part[i] = run; run += v; }
        g_off[NN] = run;
    }
    __syncthreads();
    int run = part[t];
    for (int j = 0; j < CH; j++) {
        int i = t * CH + j;
        if (i < NN) { g_off[i] = run; g_cur[i] = run; run += g_degl[i]; }
    }
}

// ================= deterministic order-preserving compaction =================
__global__ void compact_kernel() {
    int e = blockIdx.x * 256 + threadIdx.x;
    bool m = (e < EE) && g_emask8[e];
    int wid = threadIdx.x >> 5, lane = threadIdx.x & 31;
    unsigned bal = __ballot_sync(0xFFFFFFFFu, m);
    __shared__ int wcnt[8];
    if (lane == 0) wcnt[wid] = __popc(bal);
    __syncthreads();
    int woff = 0;
    for (int i = 0; i < wid; i++) woff += wcnt[i];
    if (m) {
        int pos = g_blkoff[blockIdx.x] + woff + __popc(bal & ((1u << lane) - 1));
        if (pos < MAXL) g_live[pos] = e;
    }
}

// ================= CSR scatter of compact indices by src node =================
__global__ void csr_scatter_kernel(const int* __restrict__ src) {
    int c = blockIdx.x * 256 + threadIdx.x;
    if (c < g_nlive) {
        int e = g_live[c];
        int p = atomicAdd(&g_cur[src[e]], 1);
        g_elist[p] = c;
    }
}

// ================= gather + split live ef rows =================
__global__ void gather_split_kernel(const float* __restrict__ ef) {
    int nl = g_nlive;
    size_t total = (size_t)nl * 128;
    size_t stride = (size_t)gridDim.x * blockDim.x;
    for (size_t id = (size_t)blockIdx.x * blockDim.x + threadIdx.x; id < total; id += stride) {
        int c = (int)(id >> 7), j = (int)(id & 127);
        int e = g_live[c];
        float4 x = reinterpret_cast<const float4*>(ef)[(size_t)e * 128 + j];
        __nv_bfloat162 h0 = __floats2bfloat162_rn(x.x, x.y);
        __nv_bfloat162 h1 = __floats2bfloat162_rn(x.z, x.w);
        uint2 hv, lv;
        hv.x = *reinterpret_cast<uint32_t*>(&h0);
        hv.y = *reinterpret_cast<uint32_t*>(&h1);
        lv.x = pack2bf(x.x - __bfloat162float(h0.x), x.y - __bfloat162float(h0.y));
        lv.y = pack2bf(x.z - __bfloat162float(h1.x), x.w - __bfloat162float(h1.y));
        reinterpret_cast<uint2*>(g_cefhi)[(size_t)c * 128 + j] = hv;
        reinterpret_cast<uint2*>(g_ceflo)[(size_t)c * 128 + j] = lv;
    }
}

// ================= generic fp32 -> bf16 hi/lo split =================
__global__ void split_kernel(const float* __restrict__ X, __nv_bfloat16* __restrict__ hi,
                             __nv_bfloat16* __restrict__ lo, size_t n4)
{
    size_t i = (size_t)blockIdx.x * blockDim.x + threadIdx.x;
    if (i >= n4) return;
    float4 x = reinterpret_cast<const float4*>(X)[i];
    __nv_bfloat162 h0 = __floats2bfloat162_rn(x.x, x.y);
    __nv_bfloat162 h1 = __floats2bfloat162_rn(x.z, x.w);
    uint2 hv, lv;
    hv.x = *reinterpret_cast<uint32_t*>(&h0);
    hv.y = *reinterpret_cast<uint32_t*>(&h1);
    lv.x = pack2bf(x.x - __bfloat162float(h0.x), x.y - __bfloat162float(h0.y));
    lv.y = pack2bf(x.z - __bfloat162float(h1.x), x.w - __bfloat162float(h1.y));
    reinterpret_cast<uint2*>(hi)[i] = hv;
    reinterpret_cast<uint2*>(lo)[i] = lv;
}

// ================= all 5 weight transposes + splits =================
// slots: 0=Wq(K=256), 1=Wk, 2=Wv, 3=Wo, 4=W1
__global__ void wconv_all(const float* __restrict__ Wq, const float* __restrict__ Wk,
                          const float* __restrict__ Wv, const float* __restrict__ Wo,
                          const float* __restrict__ W1)
{
    int idx = blockIdx.x * 256 + threadIdx.x;
    const int S0 = DE * DN;
    const int SB = DE * DE;
    int slot, K, r;
    const float* W;
    if (idx < S0) { slot = 0; K = DN; r = idx; W = Wq; }
    else {
        int t = idx - S0;
        slot = 1 + t / SB;
        if (slot > 4) return;
        r = t % SB; K = DE;
        W = (slot == 1) ? Wk : (slot == 2) ? Wv : (slot == 3) ? Wo : W1;
    }
    int n = r % DE, k = r / DE;
    float x = W[(size_t)k * DE + n];
    __nv_bfloat16 h = __float2bfloat16(x);
    g_whi[slot][n * K + k] = h;
    g_wlo[slot][n * K + k] = __float2bfloat16(x - __bfloat162float(h));
}

// ================= mma.sync bf16-split GEMM (pre-split A & B) =================
// C[M,512] = A[M,K] @ W^T + bias ; EPI 0: fp32 C ; EPI 4: split bf16 Chi/Clo
#define STAGE_BYTES 65536
#define GEMM_SMEM (3 * STAGE_BYTES)

template<int EPI>
__global__ __launch_bounds__(256, 1)
void mma_gemm(const __nv_bfloat16* __restrict__ Ahi, const __nv_bfloat16* __restrict__ Alo,
              const __nv_bfloat16* __restrict__ Bhi, const __nv_bfloat16* __restrict__ Blo,
              const float* __restrict__ bias, float* __restrict__ C,
              __nv_bfloat16* __restrict__ Chi, __nv_bfloat16* __restrict__ Clo,
              int Mstat, int K, const int* __restrict__ Mdyn)
{
    const int M = Mdyn ? *Mdyn : Mstat;
    const int row0 = blockIdx.y * 128;
    if (row0 >= M) return;
    extern __shared__ char sm[];
    const uint32_t sbase = (uint32_t)__cvta_generic_to_shared(sm);
    const int tid = threadIdx.x;
    const int w = tid >> 5, l = tid & 31;
    const int n0 = blockIdx.x * 128;
    const int wm = w >> 2, wn = w & 3;

    float acc[4][4][4];
    #pragma unroll
    for (int i = 0; i < 4; i++)
        #pragma unroll
        for (int j = 0; j < 4; j++)
            #pragma unroll
            for (int p = 0; p < 4; p++) acc[i][j][p] = 0.f;

    int srow[4];
    #pragma unroll
    for (int i = 0; i < 4; i++) {
        int r = row0 + (tid >> 3) + 32 * i;
        srow[i] = (r >= M) ? (M - 1) : r;
    }

    auto loadA = [&](int k0, int stage) {
        uint32_t sb = sbase + stage * STAGE_BYTES;
        #pragma unroll
        for (int i = 0; i < 4; i++) {
            int lin = tid + 256 * i;
            int r = lin >> 3, ch = lin & 7;
            uint32_t so = sb + r * 128 + (uint32_t)((ch ^ (r & 7)) * 16);
            size_t gi = (size_t)srow[i] * K + k0 + ch * 8;
            cpasync16(so, &Ahi[gi]);
            cpasync16(so + 16384, &Alo[gi]);
        }
    };
    auto loadB = [&](int k0, int stage) {
        uint32_t sb = sbase + stage * STAGE_BYTES + 32768;
        #pragma unroll
        for (int i = 0; i < 4; i++) {
            int lin = tid + 256 * i;
            int r = lin >> 3, ch = lin & 7;
            uint32_t so = sb + r * 128 + (uint32_t)((ch ^ (r & 7)) * 16);
            size_t gi = (size_t)(n0 + r) * K + k0 + ch * 8;
            cpasync16(so, &Bhi[gi]);
            cpasync16(so + 16384, &Blo[gi]);
        }
    };
    auto compute = [&](int stage) {
        uint32_t ab = sbase + stage * STAGE_BYTES;
        uint32_t bb = ab + 32768;
        #pragma unroll
        for (int ks = 0; ks < 4; ks++) {
            int kc = ks * 2;
            uint32_t ahi[4][4], alo[4][4];
            #pragma unroll
            for (int mf = 0; mf < 4; mf++) {
                int rr = wm * 64 + mf * 16 + (l & 15);
                int kch = kc + (l >> 4);
                uint32_t addr = ab + rr * 128 + (uint32_t)(((kch ^ (rr & 7))) * 16);
                ldm4(ahi[mf], addr);
                ldm4(alo[mf], addr + 16384);
            }
            uint32_t bhi[2][4], blo[2][4];
            #pragma unroll
            for (int ng = 0; ng < 2; ng++) {
                int nr = wn * 32 + ng * 16 + (l & 7) + ((l >> 4) << 3);
                int kch = kc + ((l >> 3) & 1);
                uint32_t addr = bb + nr * 128 + (uint32_t)(((kch ^ (nr & 7))) * 16);
                ldm4(bhi[ng], addr);
                ldm4(blo[ng], addr + 16384);
            }
            // pass-major ordering: same-accumulator reuse distance = 16 MMAs
            // (per-acc addition order unchanged: hi·hi, then hi·lo, then lo·hi)
            #pragma unroll
            for (int mf = 0; mf < 4; mf++)
                #pragma unroll
                for (int nf = 0; nf < 4; nf++) {
                    int ng = nf >> 1, sb2 = (nf & 1) * 2;
                    mma_bf16(acc[mf][nf], ahi[mf], bhi[ng][sb2], bhi[ng][sb2 + 1]);
                }
            #pragma unroll
            for (int mf = 0; mf < 4; mf++)
                #pragma unroll
                for (int nf = 0; nf < 4; nf++) {
                    int ng = nf >> 1, sb2 = (nf & 1) * 2;
                    mma_bf16(acc[mf][nf], ahi[mf], blo[ng][sb2], blo[ng][sb2 + 1]);
                }
            #pragma unroll
            for (int mf = 0; mf < 4; mf++)
                #pragma unroll
                for (int nf = 0; nf < 4; nf++) {
                    int ng = nf >> 1, sb2 = (nf & 1) * 2;
                    mma_bf16(acc[mf][nf], alo[mf], bhi[ng][sb2], bhi[ng][sb2 + 1]);
                }
        }
    };

    const int nch = K >> 6;
    loadA(0, 0); loadB(0, 0); cp_commit();
    if (nch > 1) { loadA(64, 1); loadB(64, 1); cp_commit(); }
    else cp_commit();
    for (int c = 0; c < nch; c++) {
        __syncthreads();
        if (c + 2 < nch) { loadA((c + 2) * 64, (c + 2) % 3); loadB((c + 2) * 64, (c + 2) % 3); }
        cp_commit();
        CP_WAIT(2);
        __syncthreads();
        compute(c % 3);
    }

    #pragma unroll
    for (int mf = 0; mf < 4; mf++) {
        int gr0 = row0 + wm * 64 + mf * 16 + (l >> 2);
        #pragma unroll
        for (int nf = 0; nf < 4; nf++) {
            int gc = n0 + wn * 32 + nf * 8 + (l & 3) * 2;
            float b0 = bias[gc], b1 = bias[gc + 1];
            #pragma unroll
            for (int h = 0; h < 2; h++) {
                int grow = gr0 + 8 * h;
                if (grow >= M) continue;
                float v0 = acc[mf][nf][2 * h] + b0;
                float v1 = acc[mf][nf][2 * h + 1] + b1;
                if (EPI == 4) {
                    __nv_bfloat162 hh = __floats2bfloat162_rn(v0, v1);
                    uint32_t hw = *reinterpret_cast<uint32_t*>(&hh);
                    uint32_t lw = pack2bf(v0 - __bfloat162float(hh.x), v1 - __bfloat162float(hh.y));
                    *reinterpret_cast<uint32_t*>(&Chi[(size_t)grow * DE + gc]) = hw;
                    *reinterpret_cast<uint32_t*>(&Clo[(size_t)grow * DE + gc]) = lw;
                } else {
                    *reinterpret_cast<float2*>(&C[(size_t)grow * DE + gc]) = make_float2(v0, v1);
                }
            }
        }
    }
}

// ================= qbk: dead-edge logit per node/head =================
__global__ void qbk_kernel(const float* __restrict__ bk) {
    int n = blockIdx.x * 8 + (threadIdx.x >> 5);
    int lane = threadIdx.x & 31;
    if (n >= NN) return;
    const float4* qr = reinterpret_cast<const float4*>(g_q + (size_t)n * DE);
    const float4* br = reinterpret_cast<const float4*>(bk);
    float s = 0.f;
    int base = lane * 4;
    #pragma unroll
    for (int j = 0; j < 4; j++) {
        float4 a = qr[base + j], b = br[base + j];
        s += a.x * b.x + a.y * b.y + a.z * b.z + a.w * b.w;
    }
    s += __shfl_xor_sync(0xFFFFFFFFu, s, 1);
    s += __shfl_xor_sync(0xFFFFFFFFu, s, 2);
    if ((lane & 3) == 0) g_qbk[(size_t)n * NH + (lane >> 2)] = s * 0.125f;
}

// ================= attention logits: one warp per live edge =================
__global__ void attn_live_kernel(const int* __restrict__ src) {
    int c = blockIdx.x * 8 + (threadIdx.x >> 5);
    int lane = threadIdx.x & 31;
    if (c >= g_nlive) return;
    int e = g_live[c];
    const float4* qr = reinterpret_cast<const float4*>(g_q + (size_t)src[e] * DE);
    const float4* kr = reinterpret_cast<const float4*>(g_kc + (size_t)c * DE);
    float s = 0.f;
    int base = lane * 4;
    #pragma unroll
    for (int j = 0; j < 4; j++) {
        float4 a = qr[base + j], b = kr[base + j];
        s += a.x * b.x + a.y * b.y + a.z * b.z + a.w * b.w;
    }
    s += __shfl_xor_sync(0xFFFFFFFFu, s, 1);
    s += __shfl_xor_sync(0xFFFFFFFFu, s, 2);
    if ((lane & 3) == 0) g_scc[(size_t)c * NH + (lane >> 2)] = s * 0.125f;
}

// ================= segment softmax + aggregation (live + analytic dead) =================
__global__ void softmax_agg_kernel(const float* __restrict__ bv) {
    int n = blockIdx.x;
    int off = g_off[n];
    int degl = g_off[n + 1] - off;
    int ndead = g_degt[n] - degl;
    int tid = threadIdx.x;
    int wid = tid >> 5, lane = tid & 31;
    int d0 = tid * 2;

    if (degl + ndead == 0) {
        *reinterpret_cast<float2*>(g_agg + (size_t)n * DE + d0) = make_float2(0.f, 0.f);
        return;
    }
    __shared__ float m_sh[NH], d_sh[NH], cdead_sh[NH];
    __shared__ float attn_sh[64 * NH];
    {
        float qb = g_qbk[(size_t)n * NH + wid];
        float mx = -INFINITY;
        for (int i = lane; i < degl; i += 32) {
            int c = g_elist[off + i];
            mx = fmaxf(mx, g_scc[(size_t)c * NH + wid]);
        }
        #pragma unroll
        for (int o = 16; o; o >>= 1) mx = fmaxf(mx, __shfl_xor_sync(0xFFFFFFFFu, mx, o));
        if (ndead > 0) mx = fmaxf(mx, qb);
        float sm = 0.f;
        for (int i = lane; i < degl; i += 32) {
            int c = g_elist[off + i];
            sm += expf(g_scc[(size_t)c * NH + wid] - mx);
        }
        #pragma unroll
        for (int o = 16; o; o >>= 1) sm += __shfl_xor_sync(0xFFFFFFFFu, sm, o);
        if (lane == 0) {
            float dterm = (ndead > 0) ? (float)ndead * expf(qb - mx) : 0.f;
            float den = sm + dterm;
            m_sh[wid] = mx; d_sh[wid] = den; cdead_sh[wid] = dterm / den;
        }
    }
    __syncthreads();
    float2 acc = make_float2(0.f, 0.f);
    int h = d0 >> 6;
    for (int base = 0; base < degl; base += 64) {
        int cnt = min(64, degl - base);
        __syncthreads();
        for (int idx = tid; idx < cnt * NH; idx += 256) {
            int j = idx >> 3, hh = idx & 7;
            int c = g_elist[off + base + j];
            attn_sh[idx] = expf(g_scc[(size_t)c * NH + hh] - m_sh[hh]) / d_sh[hh];
        }
        __syncthreads();
        for (int j = 0; j < cnt; j++) {
            int c = g_elist[off + base + j];
            float a = attn_sh[j * NH + h];
            float2 vv = *reinterpret_cast<const float2*>(g_vc + (size_t)c * DE + d0);
            acc.x += a * vv.x;
            acc.y += a * vv.y;
        }
    }
    float cd = cdead_sh[h];
    acc.x += cd * bv[d0];
    acc.y += cd * bv[d0 + 1];
    *reinterpret_cast<float2*>(g_agg + (size_t)n * DE + d0) = acc;
}

// ================= per-node classifier (dead-edge output) =================
__global__ void classify_node_kernel(const float* __restrict__ W2, const float* __restrict__ b2) {
    __shared__ float W2s[DE * NC];
    int tid = threadIdx.x;
    for (int i = tid; i < DE * NC; i += 256) W2s[i] = W2[i];
    __syncthreads();
    int n = blockIdx.x * 8 + (tid >> 5);
    if (n >= NN) return;
    int lane = tid & 31;
    const float* ntr = g_nt + (size_t)n * DE;
    float p[NC];
    #pragma unroll
    for (int c = 0; c < NC; c++) p[c] = 0.f;
    for (int k = lane; k < DE; k += 32) {
        float hv = gelu_exact(ntr[k]);
        const float* wk = &W2s[k * NC];
        #pragma unroll
        for (int c = 0; c < NC; c++) p[c] += hv * wk[c];
    }
    #pragma unroll
    for (int c = 0; c < NC; c++) {
        #pragma unroll
        for (int o = 16; o; o >>= 1) p[c] += __shfl_xor_sync(0xFFFFFFFFu, p[c], o);
    }
    if (lane == 0) {
        #pragma unroll
        for (int c = 0; c < NC; c++) g_outc[(size_t)n * NC + c] = p[c] + b2[c];
    }
}

// ================= live-edge output: gelu(nt[src]+efW1) @ W2 =================
__global__ void live_out_kernel(const int* __restrict__ src, const float* __restrict__ W2,
                                const float* __restrict__ b2, float* __restrict__ out) {
    __shared__ float W2s[DE * NC];
    int tid = threadIdx.x;
    for (int i = tid; i < DE * NC; i += 256) W2s[i] = W2[i];
    __syncthreads();
    int c = blockIdx.x * 8 + (tid >> 5);
    if (c >= g_nlive) return;
    int e = g_live[c];
    int lane = tid & 31;
    const float* ntr = g_nt + (size_t)src[e] * DE;
    const float* fr = g_efw1 + (size_t)c * DE;
    float p[NC];
    #pragma unroll
    for (int cc = 0; cc < NC; cc++) p[cc] = 0.f;
    for (int k = lane; k < DE; k += 32) {
        float hv = gelu_exact(ntr[k] + fr[k]);
        const float* wk = &W2s[k * NC];
        #pragma unroll
        for (int cc = 0; cc < NC; cc++) p[cc] += hv * wk[cc];
    }
    #pragma unroll
    for (int cc = 0; cc < NC; cc++) {
        #pragma unroll
        for (int o = 16; o; o >>= 1) p[cc] += __shfl_xor_sync(0xFFFFFFFFu, p[cc], o);
    }
    if (lane == 0) {
        #pragma unroll
        for (int cc = 0; cc < NC; cc++) out[(size_t)e * NC + cc] = p[cc] + b2[cc];
    }
}

// ================= dead-edge output: copy per-node classifier =================
__global__ void dead_out_kernel(const int* __restrict__ src, float* __restrict__ out) {
    int e = blockIdx.x * 256 + threadIdx.x;
    if (e >= EE || g_emask8[e]) return;
    const float* s = g_outc + (size_t)src[e] * NC;
    float* d = out + (size_t)e * NC;
    #pragma unroll
    for (int c = 0; c < NC; c++) d[c] = s[c];
}

// ================= host launcher (stream-fork DAG) =================
extern "C" void kernel_launch(void* const* d_in, const int* in_sizes, int n_in,
                              void* d_out, int out_size)
{
    const float* node_features = (const float*)d_in[0];
    const float* edge_features = (const float*)d_in[1];
    const int*   edge_index    = (const int*)d_in[2];
    const float* nw = (const float*)d_in[4];
    const float* nb = (const float*)d_in[5];
    const float* ew = (const float*)d_in[6];
    const float* eb = (const float*)d_in[7];
    const float* Wq = (const float*)d_in[8];  const float* bq = (const float*)d_in[9];
    const float* Wk = (const float*)d_in[10]; const float* bk = (const float*)d_in[11];
    const float* Wv = (const float*)d_in[12]; const float* bv = (const float*)d_in[13];
    const float* Wo = (const float*)d_in[14]; const float* bo = (const float*)d_in[15];
    const float* W1 = (const float*)d_in[16]; const float* b1 = (const float*)d_in[17];
    const float* W2 = (const float*)d_in[18]; const float* b2 = (const float*)d_in[19];
    float* out = (float*)d_out;
    const int* src = edge_index;
    const int* dst = edge_index + EE;

    float *qp, *kcp, *vcp, *efw1p, *aggp, *ntp, *nsp, *esp, *zbp;
    __nv_bfloat16 *whi, *wlo, *cefhi, *ceflo, *nfhi, *nflo, *aghi, *aglo, *awhi, *awlo;
    int *nlp;
    cudaGetSymbolAddress((void**)&qp,    g_q);
    cudaGetSymbolAddress((void**)&kcp,   g_kc);
    cudaGetSymbolAddress((void**)&vcp,   g_vc);
    cudaGetSymbolAddress((void**)&efw1p, g_efw1);
    cudaGetSymbolAddress((void**)&aggp,  g_agg);
    cudaGetSymbolAddress((void**)&ntp,   g_nt);
    cudaGetSymbolAddress((void**)&nsp,   g_nscore);
    cudaGetSymbolAddress((void**)&esp,   g_escore);
    cudaGetSymbolAddress((void**)&zbp,   g_zb);
    cudaGetSymbolAddress((void**)&whi,   g_whi);
    cudaGetSymbolAddress((void**)&wlo,   g_wlo);
    cudaGetSymbolAddress((void**)&cefhi, g_cefhi);
    cudaGetSymbolAddress((void**)&ceflo, g_ceflo);
    cudaGetSymbolAddress((void**)&nfhi,  g_nfhi);
    cudaGetSymbolAddress((void**)&nflo,  g_nflo);
    cudaGetSymbolAddress((void**)&aghi,  g_agghi);
    cudaGetSymbolAddress((void**)&aglo,  g_agglo);
    cudaGetSymbolAddress((void**)&awhi,  g_awhi);
    cudaGetSymbolAddress((void**)&awlo,  g_awlo);
    cudaGetSymbolAddress((void**)&nlp,   g_nlive);

    cudaFuncSetAttribute((const void*)mma_gemm<0>, cudaFuncAttributeMaxDynamicSharedMemorySize, GEMM_SMEM);
    cudaFuncSetAttribute((const void*)mma_gemm<4>, cudaFuncAttributeMaxDynamicSharedMemorySize, GEMM_SMEM);

    const size_t SB = (size_t)DE * DE;

    // ---- stream / event setup (capture-safe fork from legacy stream) ----
    cudaStream_t sA = 0;   // legacy stream = capture origin
    cudaStream_t sB, sC;
    cudaStreamCreateWithFlags(&sB, cudaStreamNonBlocking);
    cudaStreamCreateWithFlags(&sC, cudaStreamNonBlocking);
    enum { EV_ROOT, EV_WCONV, EV_NSC, EV_QBK, EV_CMP, EV_GATHER, EV_CSR, EV_EFW1, EV_CLS, EV_DEAD, NEV };
    cudaEvent_t ev[NEV];
    for (int i = 0; i < NEV; i++) cudaEventCreateWithFlags(&ev[i], cudaEventDisableTiming);

    // fork: B and C branch off the legacy stream
    cudaEventRecord(ev[EV_ROOT], sA);
    cudaStreamWaitEvent(sB, ev[EV_ROOT], 0);
    cudaStreamWaitEvent(sC, ev[EV_ROOT], 0);

    // ---- stream B: weight splits -> (wait compact) csr -> (wait gather) efw1 GEMM -> (wait classify) dead_out
    wconv_all<<<(DE * DN + 4 * DE * DE + 255) / 256, 256, 0, sB>>>(Wq, Wk, Wv, Wo, W1);
    cudaEventRecord(ev[EV_WCONV], sB);

    // ---- stream C: nf split -> node scorer -> (wait wconv) q GEMM -> qbk
    split_kernel<<<((size_t)NN * DN / 4 + 255) / 256, 256, 0, sC>>>(node_features, nfhi, nflo, (size_t)NN * DN / 4);
    score_kernel<<<(NN + 7) / 8, 256, 0, sC>>>(node_features, nw, nb, nsp, NN, DN);
    cudaEventRecord(ev[EV_NSC], sC);
    cudaStreamWaitEvent(sC, ev[EV_WCONV], 0);
    dim3 gq(4, (NN + 127) / 128);
    mma_gemm<0><<<gq, 256, GEMM_SMEM, sC>>>(nfhi, nflo, whi + 0 * SB, wlo + 0 * SB, bq,
                                            qp, nullptr, nullptr, NN, DN, nullptr);
    qbk_kernel<<<(NN + 7) / 8, 256, 0, sC>>>(bk);
    cudaEventRecord(ev[EV_QBK], sC);

    // ---- stream A (legacy): zero, edge scorer, topk, mask, scans, compact, gather, k/v GEMMs, attention chain
    zero_kernel<<<(NN + 255) / 256, 256, 0, sA>>>();
    score_kernel<<<(EE + 7) / 8, 256, 0, sA>>>(edge_features, ew, eb, esp, EE, DE);
    cudaStreamWaitEvent(sA, ev[EV_NSC], 0);
    topk_kernel<<<2, 1024, 0, sA>>>();
    emask_count_kernel<<<625, 256, 0, sA>>>(src, dst);
    scan2_kernel<<<1, 1024, 0, sA>>>();
    compact_kernel<<<625, 256, 0, sA>>>();
    cudaEventRecord(ev[EV_CMP], sA);
    gather_split_kernel<<<2048, 256, 0, sA>>>(edge_features);
    cudaEventRecord(ev[EV_GATHER], sA);

    // B: csr_scatter (needs compact + scan2)
    cudaStreamWaitEvent(sB, ev[EV_CMP], 0);
    csr_scatter_kernel<<<(MAXL + 255) / 256, 256, 0, sB>>>(src);
    cudaEventRecord(ev[EV_CSR], sB);
    // B: efw1 GEMM (needs gather + wconv[same stream])
    cudaStreamWaitEvent(sB, ev[EV_GATHER], 0);
    dim3 gl(4, MAXL / 128);
    mma_gemm<0><<<gl, 256, GEMM_SMEM, sB>>>(cefhi, ceflo, whi + 4 * SB, wlo + 4 * SB, zbp,
                                            efw1p, nullptr, nullptr, 0, DE, nlp);
    cudaEventRecord(ev[EV_EFW1], sB);

    // A: k/v GEMMs (need wconv)
    cudaStreamWaitEvent(sA, ev[EV_WCONV], 0);
    mma_gemm<0><<<gl, 256, GEMM_SMEM, sA>>>(cefhi, ceflo, whi + 1 * SB, wlo + 1 * SB, bk,
                                            kcp, nullptr, nullptr, 0, DE, nlp);
    mma_gemm<0><<<gl, 256, GEMM_SMEM, sA>>>(cefhi, ceflo, whi + 2 * SB, wlo + 2 * SB, bv,
                                            vcp, nullptr, nullptr, 0, DE, nlp);

    // A: attention (needs q from C, csr from B)
    cudaStreamWaitEvent(sA, ev[EV_QBK], 0);
    attn_live_kernel<<<(MAXL + 7) / 8, 256, 0, sA>>>(src);
    cudaStreamWaitEvent(sA, ev[EV_CSR], 0);
    softmax_agg_kernel<<<NN, 256, 0, sA>>>(bv);

    // A: node-side chain
    split_kernel<<<((size_t)NN * DE / 4 + 255) / 256, 256, 0, sA>>>(aggp, aghi, aglo, (size_t)NN * DE / 4);
    mma_gemm<4><<<gq, 256, GEMM_SMEM, sA>>>(aghi, aglo, whi + 3 * SB, wlo + 3 * SB, bo,
                                            nullptr, awhi, awlo, NN, DE, nullptr);
    mma_gemm<0><<<gq, 256, GEMM_SMEM, sA>>>(awhi, awlo, whi + 4 * SB, wlo + 4 * SB, b1,
                                            ntp, nullptr, nullptr, NN, DE, nullptr);
    classify_node_kernel<<<(NN + 7) / 8, 256, 0, sA>>>(W2, b2);
    cudaEventRecord(ev[EV_CLS], sA);

    // B: dead-edge output (needs classify + emask)
    cudaStreamWaitEvent(sB, ev[EV_CLS], 0);
    dead_out_kernel<<<(EE + 255) / 256, 256, 0, sB>>>(src, out);
    cudaEventRecord(ev[EV_DEAD], sB);

    // A: live-edge output (needs nt + efw1)
    cudaStreamWaitEvent(sA, ev[EV_EFW1], 0);
    live_out_kernel<<<(MAXL + 7) / 8, 256, 0, sA>>>(src, W2, b2, out);

    // join everything back into the legacy stream
    cudaStreamWaitEvent(sA, ev[EV_DEAD], 0);

    // cleanup: only destroy when NOT capturing (destroying a captured stream invalidates capture)
    cudaStreamCaptureStatus cap = cudaStreamCaptureStatusNone;
    cudaStreamIsCapturing(sA, &cap);
    if (cap == cudaStreamCaptureStatusNone) {
        cudaStreamDestroy(sB);
        cudaStreamDestroy(sC);
        for (int i = 0; i < NEV; i++) cudaEventDestroy(ev[i]);
    }
}